// round 3
// baseline (speedup 1.0000x reference)
#include <cuda_runtime.h>
#include <cuda_bf16.h>
#include <math.h>
#include <stdint.h>

// Problem constants
#define BATCH 32
#define SEQ   512
#define IN_D  512
#define HID   1024
#define G3    3072   // 3*HID
#define NCTA  128    // persistent scan grid size (must all be co-resident)

typedef unsigned long long ull;

// packed f32x2 FMA: d = a*b + d (elementwise on two packed fp32)
#define FMA2(acc, a, b) asm("fma.rn.f32x2 %0, %1, %2, %0;" : "+l"(acc) : "l"(a), "l"(b))
#define DUPF(d, x) asm("mov.b64 %0, {%1, %1};" : "=l"(d) : "r"(__float_as_uint(x)))

__device__ __forceinline__ float psum(ull p) {
    unsigned lo, hi;
    asm("mov.b64 {%0, %1}, %2;" : "=r"(lo), "=r"(hi) : "l"(p));
    return __uint_as_float(lo) + __uint_as_float(hi);
}
__device__ __forceinline__ void unpk(ull p, float& a, float& b) {
    unsigned lo, hi;
    asm("mov.b64 {%0, %1}, %2;" : "=r"(lo), "=r"(hi) : "l"(p));
    a = __uint_as_float(lo); b = __uint_as_float(hi);
}

// ---------------------------------------------------------------------------
// Scratch (device globals; zero-initialized at module load)
// ---------------------------------------------------------------------------
__device__ float g_gx[(size_t)SEQ * BATCH * G3];   // reused for both layers
__device__ float g_y0[(size_t)SEQ * BATCH * HID];  // layer0 hidden history
__device__ float g_y1[(size_t)SEQ * BATCH * HID];  // layer1 hidden history
__device__ float g_h0[BATCH * HID];                // zeros, never written

// grid barrier state
__device__ unsigned g_count;   // zero-init
__device__ unsigned g_gen;     // zero-init, monotonic across replays (relative compare)

// ---------------------------------------------------------------------------
// SGEMM (fp32 via FFMA2, NT): C[m][n] = sum_k A[m][k]*W[n][k] + bias[n]
// A row offset = (m>>5)*a_s0 + (m&31)*a_s1 ; C row offset = (m>>5)*c_s0 + (m&31)*c_s1
// BM=BN=128, BK=16, 256 threads, 8x8 per thread (acc packed along n).
// ---------------------------------------------------------------------------
__global__ __launch_bounds__(256)
void sgemm_nt(const float* __restrict__ A, const float* __restrict__ W,
              const float* __restrict__ bias, float* __restrict__ C,
              int K,
              int a_s0, int a_s1, int c_s0, int c_s1)
{
    __shared__ float As[16][132];
    __shared__ float Ws[16][132];

    const int bm = blockIdx.y * 128;
    const int bn = blockIdx.x * 128;
    const int tid = threadIdx.x;
    const int tx = tid & 15;        // n group
    const int ty = tid >> 4;        // m group

    const int lr = tid >> 1;
    const int lk = (tid & 1) * 8;

    const int ma = bm + lr;
    const float* Arow = A + (size_t)(ma >> 5) * a_s0 + (size_t)(ma & 31) * a_s1;
    const float* Wrow = W + (size_t)(bn + lr) * K;

    ull accp[8][4];
#pragma unroll
    for (int i = 0; i < 8; i++)
#pragma unroll
        for (int j = 0; j < 4; j++) accp[i][j] = 0ull;

    for (int k0 = 0; k0 < K; k0 += 16) {
        float4 a0 = *(const float4*)(Arow + k0 + lk);
        float4 a1 = *(const float4*)(Arow + k0 + lk + 4);
        float4 w0 = *(const float4*)(Wrow + k0 + lk);
        float4 w1 = *(const float4*)(Wrow + k0 + lk + 4);

        __syncthreads();
        As[lk + 0][lr] = a0.x; As[lk + 1][lr] = a0.y;
        As[lk + 2][lr] = a0.z; As[lk + 3][lr] = a0.w;
        As[lk + 4][lr] = a1.x; As[lk + 5][lr] = a1.y;
        As[lk + 6][lr] = a1.z; As[lk + 7][lr] = a1.w;
        Ws[lk + 0][lr] = w0.x; Ws[lk + 1][lr] = w0.y;
        Ws[lk + 2][lr] = w0.z; Ws[lk + 3][lr] = w0.w;
        Ws[lk + 4][lr] = w1.x; Ws[lk + 5][lr] = w1.y;
        Ws[lk + 6][lr] = w1.z; Ws[lk + 7][lr] = w1.w;
        __syncthreads();

#pragma unroll
        for (int kk = 0; kk < 16; kk++) {
            float a[8];
            *(float4*)(a)     = *(const float4*)&As[kk][ty * 8];
            *(float4*)(a + 4) = *(const float4*)&As[kk][ty * 8 + 4];
            ulonglong2 wA = *(const ulonglong2*)&Ws[kk][tx * 8];
            ulonglong2 wB = *(const ulonglong2*)&Ws[kk][tx * 8 + 4];
            ull wp0 = wA.x, wp1 = wA.y, wp2 = wB.x, wp3 = wB.y;
#pragma unroll
            for (int i = 0; i < 8; i++) {
                ull ad; DUPF(ad, a[i]);
                FMA2(accp[i][0], ad, wp0);
                FMA2(accp[i][1], ad, wp1);
                FMA2(accp[i][2], ad, wp2);
                FMA2(accp[i][3], ad, wp3);
            }
        }
    }

    const int nbase = bn + tx * 8;
    float bv[8];
    *(float4*)(bv)     = *(const float4*)(bias + nbase);
    *(float4*)(bv + 4) = *(const float4*)(bias + nbase + 4);

#pragma unroll
    for (int i = 0; i < 8; i++) {
        const int m = bm + ty * 8 + i;
        float* crow = C + (size_t)(m >> 5) * c_s0 + (size_t)(m & 31) * c_s1 + nbase;
        float o[8];
#pragma unroll
        for (int j = 0; j < 4; j++) unpk(accp[i][j], o[2 * j], o[2 * j + 1]);
        float4 s0, s1;
        s0.x = o[0] + bv[0]; s0.y = o[1] + bv[1]; s0.z = o[2] + bv[2]; s0.w = o[3] + bv[3];
        s1.x = o[4] + bv[4]; s1.y = o[5] + bv[5]; s1.z = o[6] + bv[6]; s1.w = o[7] + bv[7];
        *(float4*)(crow)     = s0;
        *(float4*)(crow + 4) = s1;
    }
}

// ---------------------------------------------------------------------------
// grid-wide barrier (all NCTA CTAs co-resident)
// ---------------------------------------------------------------------------
__device__ __forceinline__ void grid_barrier()
{
    __syncthreads();
    if (threadIdx.x == 0) {
        unsigned old = *(volatile unsigned*)&g_gen;
        __threadfence();
        if (atomicAdd(&g_count, 1u) == NCTA - 1) {
            g_count = 0;
            __threadfence();
            atomicAdd(&g_gen, 1u);
        } else {
            while (*(volatile unsigned*)&g_gen == old) __nanosleep(64);
        }
        __threadfence();
    }
    __syncthreads();
}

// ---------------------------------------------------------------------------
// Persistent GRU layer scan: 512 steps in one launch.
// grid = 128 CTAs, block = 256. CTA c owns hidden cols [c*8, c*8+8).
// Warp w -> col j = c*8+w (weights for all 3 gates held in registers).
// Lane l -> k-slice [l*32, l*32+32). Butterfly reduction; lane b does the
// gate update for batch b and writes y[s][b][j].
// ---------------------------------------------------------------------------
__global__ __launch_bounds__(256, 1)
void gru_scan(const float* __restrict__ gx,   // [512][32][3072] (bias folded)
              const float* __restrict__ Whh,  // [3072][1024]
              const float* __restrict__ h0,   // [32][1024] zeros
              float* __restrict__ y)          // [512][32][1024]
{
    extern __shared__ float smem[];
    float4*     smh4 = (float4*)smem;                 // 8192 float4 (32 rows x 256 chunks)
    ulonglong2* smh2 = (ulonglong2*)smem;
    float*      gxs  = smem + 8192 * 4;               // [32][28]

    const int tid = threadIdx.x;
    const int w   = tid >> 5;
    const int l   = tid & 31;
    const int lm  = l & 7;
    const int cta = blockIdx.x;
    const int j   = cta * 8 + w;

    // Load this warp-lane's weight slices into registers (held for all 512 steps)
    ull wr[16], wz[16], wn[16];
    {
        const float* br = Whh + (size_t)j * HID + (size_t)l * 32;
        const float* bz = br + (size_t)HID * HID;
        const float* bn_ = bz + (size_t)HID * HID;
#pragma unroll
        for (int i = 0; i < 8; i++) {
            ulonglong2 u = *(const ulonglong2*)(br + i * 4);
            wr[2 * i] = u.x; wr[2 * i + 1] = u.y;
        }
#pragma unroll
        for (int i = 0; i < 8; i++) {
            ulonglong2 u = *(const ulonglong2*)(bz + i * 4);
            wz[2 * i] = u.x; wz[2 * i + 1] = u.y;
        }
#pragma unroll
        for (int i = 0; i < 8; i++) {
            ulonglong2 u = *(const ulonglong2*)(bn_ + i * 4);
            wn[2 * i] = u.x; wn[2 * i + 1] = u.y;
        }
    }

    // precomputed swizzled smem chunk offsets for this lane
    int hoff[8];
#pragma unroll
    for (int i = 0; i < 8; i++) hoff[i] = l * 8 + (i ^ lm);

    const int sw_tid = tid ^ ((tid >> 3) & 7);   // staging swizzle slot

    for (int s = 0; s < SEQ; s++) {
        const float* hin = (s == 0) ? h0 : (y + (size_t)(s - 1) * (BATCH * HID));
        const float* gxsrc = gx + (size_t)s * (BATCH * G3);

        // stage h (32 rows x 256 chunks), swizzled
#pragma unroll 8
        for (int b = 0; b < 32; b++) {
            float4 v = *(const float4*)(hin + (size_t)b * HID + tid * 4);
            smh4[b * 256 + sw_tid] = v;
        }
        // stage this CTA's gx slice: [32 b][3 gates][8 cols]
        if (tid < 192) {
            int bb = tid / 6, rem = tid % 6, g = rem >> 1, half = rem & 1;
            float4 v = *(const float4*)(gxsrc + (size_t)bb * G3 + g * HID + cta * 8 + half * 4);
            *(float4*)(gxs + bb * 28 + g * 8 + half * 4) = v;
        }
        const float hp = hin[(size_t)l * HID + j];   // h_prev[b=l][j]
        __syncthreads();

        float myar = 0.f, myaz = 0.f, myan = 0.f;
#pragma unroll 2
        for (int b = 0; b < 32; b++) {
            ull ar = 0ull, az = 0ull, an = 0ull;
            const ulonglong2* hrow = smh2 + b * 256;
#pragma unroll
            for (int i = 0; i < 8; i++) {
                ulonglong2 h2 = hrow[hoff[i]];
                FMA2(ar, h2.x, wr[2 * i]); FMA2(ar, h2.y, wr[2 * i + 1]);
                FMA2(az, h2.x, wz[2 * i]); FMA2(az, h2.y, wz[2 * i + 1]);
                FMA2(an, h2.x, wn[2 * i]); FMA2(an, h2.y, wn[2 * i + 1]);
            }
            float sr = psum(ar), sz = psum(az), sn = psum(an);
#pragma unroll
            for (int off = 16; off; off >>= 1) {
                sr += __shfl_xor_sync(0xffffffffu, sr, off);
                sz += __shfl_xor_sync(0xffffffffu, sz, off);
                sn += __shfl_xor_sync(0xffffffffu, sn, off);
            }
            if (l == b) { myar = sr; myaz = sz; myan = sn; }
        }

        // gate update for batch b = l, column j
        const float gxr = gxs[l * 28 + w];
        const float gxz = gxs[l * 28 + 8 + w];
        const float gxn = gxs[l * 28 + 16 + w];
        const float r = 1.f / (1.f + __expf(-(gxr + myar)));
        const float z = 1.f / (1.f + __expf(-(gxz + myaz)));
        const float npre = fmaf(r, myan, gxn + myan);
        const float e2 = __expf(2.f * npre);
        const float n = 1.f - 2.f / (e2 + 1.f);
        const float hnew = (1.f - z) * n + z * hp;
        y[(size_t)s * (BATCH * HID) + (size_t)l * HID + j] = hnew;

        __threadfence();
        grid_barrier();
    }
}

// ---------------------------------------------------------------------------
// Tail: new_hidden = stack([h_last0, h_last1])
// ---------------------------------------------------------------------------
__global__ void copy_tail(const float* __restrict__ h0,
                          const float* __restrict__ h1,
                          float* __restrict__ dst)
{
    int i = blockIdx.x * blockDim.x + threadIdx.x;   // 0..32767
    dst[i]               = h0[i];
    dst[BATCH * HID + i] = h1[i];
}

// ---------------------------------------------------------------------------
// kernel_launch
// ---------------------------------------------------------------------------
extern "C" void kernel_launch(void* const* d_in, const int* in_sizes, int n_in,
                              void* d_out, int out_size)
{
    const float* x    = (const float*)d_in[0];
    const float* Wih0 = (const float*)d_in[1];
    const float* Whh0 = (const float*)d_in[2];
    const float* b0   = (const float*)d_in[3];
    const float* Wih1 = (const float*)d_in[4];
    const float* Whh1 = (const float*)d_in[5];
    const float* b1   = (const float*)d_in[6];
    const float* Wlin = (const float*)d_in[7];
    const float* blin = (const float*)d_in[8];
    float* out = (float*)d_out;

    float *gx, *y0, *y1, *h0;
    cudaGetSymbolAddress((void**)&gx, g_gx);
    cudaGetSymbolAddress((void**)&y0, g_y0);
    cudaGetSymbolAddress((void**)&y1, g_y1);
    cudaGetSymbolAddress((void**)&h0, g_h0);

    const int SCAN_SMEM = 8192 * 16 + 32 * 28 * 4;   // 134656 bytes
    cudaFuncSetAttribute(gru_scan, cudaFuncAttributeMaxDynamicSharedMemorySize, SCAN_SMEM);

    // 1) GX = x @ Wih0^T + b0, time-major [t][b][:]
    sgemm_nt<<<dim3(G3 / 128, (SEQ * BATCH) / 128), 256>>>(
        x, Wih0, b0, gx, IN_D,
        /*a_s0=*/IN_D, /*a_s1=*/SEQ * IN_D,
        /*c_s0=*/BATCH * G3, /*c_s1=*/G3);

    // 2) layer-0 scan (persistent)
    gru_scan<<<NCTA, 256, SCAN_SMEM>>>(gx, Whh0, h0, y0);

    // 3) GX = Y0 @ Wih1^T + b1
    sgemm_nt<<<dim3(G3 / 128, (SEQ * BATCH) / 128), 256>>>(
        y0, Wih1, b1, gx, HID,
        /*a_s0=*/BATCH * HID, /*a_s1=*/HID,
        /*c_s0=*/BATCH * G3, /*c_s1=*/G3);

    // 4) layer-1 scan (persistent)
    gru_scan<<<NCTA, 256, SCAN_SMEM>>>(gx, Whh1, h0, y1);

    // 5) out[b][t][:] = Y1[t][b][:] @ Wlin^T + blin
    sgemm_nt<<<dim3(IN_D / 128, (SEQ * BATCH) / 128), 256>>>(
        y1, Wlin, blin, out, HID,
        /*a_s0=*/BATCH * HID, /*a_s1=*/HID,
        /*c_s0=*/IN_D, /*c_s1=*/SEQ * IN_D);

    // 6) new_hidden tail
    copy_tail<<<128, 256>>>(y0 + (size_t)(SEQ - 1) * BATCH * HID,
                            y1 + (size_t)(SEQ - 1) * BATCH * HID,
                            out + (size_t)BATCH * SEQ * IN_D);
}

// round 5
// speedup vs baseline: 1.1441x; 1.1441x over previous
#include <cuda_runtime.h>
#include <cuda_bf16.h>
#include <math.h>
#include <stdint.h>

// Problem constants
#define BATCH 32
#define SEQ   512
#define IN_D  512
#define HID   1024
#define G3    3072   // 3*HID
#define NCTA  128    // persistent scan grid size

typedef unsigned long long ull;

// packed f32x2 FMA
#define FMA2(acc, a, b) asm("fma.rn.f32x2 %0, %1, %2, %0;" : "+l"(acc) : "l"(a), "l"(b))

__device__ __forceinline__ float psum(ull p) {
    unsigned lo, hi;
    asm("mov.b64 {%0, %1}, %2;" : "=r"(lo), "=r"(hi) : "l"(p));
    return __uint_as_float(lo) + __uint_as_float(hi);
}

__device__ __forceinline__ uint32_t smem_u32(const void* p) {
    uint32_t a;
    asm("{ .reg .u64 t; cvta.to.shared.u64 t, %1; cvt.u32.u64 %0, t; }" : "=r"(a) : "l"(p));
    return a;
}

// mma.sync / ldmatrix / cp.async (baseline ISA, works on sm_103 target)
#define LDSM_X4(r0, r1, r2, r3, addr) \
    asm volatile("ldmatrix.sync.aligned.m8n8.x4.shared.b16 {%0,%1,%2,%3}, [%4];" \
        : "=r"(r0), "=r"(r1), "=r"(r2), "=r"(r3) : "r"(addr))
#define LDSM_X2(r0, r1, addr) \
    asm volatile("ldmatrix.sync.aligned.m8n8.x2.shared.b16 {%0,%1}, [%2];" \
        : "=r"(r0), "=r"(r1) : "r"(addr))
#define MMA_BF16(d, a, b) \
    asm volatile("mma.sync.aligned.m16n8k16.row.col.f32.bf16.bf16.f32 " \
        "{%0,%1,%2,%3}, {%4,%5,%6,%7}, {%8,%9}, {%0,%1,%2,%3};" \
        : "+f"((d)[0]), "+f"((d)[1]), "+f"((d)[2]), "+f"((d)[3]) \
        : "r"((a)[0]), "r"((a)[1]), "r"((a)[2]), "r"((a)[3]), "r"((b)[0]), "r"((b)[1]))
#define CP16(dst, src) \
    asm volatile("cp.async.cg.shared.global [%0], [%1], 16;" :: "r"(dst), "l"(src))
#define CP_COMMIT() asm volatile("cp.async.commit_group;" ::: "memory")
#define CP_WAIT0()  asm volatile("cp.async.wait_group 0;" ::: "memory")

// ---------------------------------------------------------------------------
// Scratch (device globals)
// ---------------------------------------------------------------------------
__device__ float g_gx[(size_t)SEQ * BATCH * G3];
__device__ float g_y0[(size_t)SEQ * BATCH * HID];
__device__ float g_y1[(size_t)SEQ * BATCH * HID];
__device__ float g_h0[BATCH * HID];                        // zeros
__device__ __nv_bfloat16 g_ah[(size_t)SEQ * BATCH * HID];  // A hi [M][K] row-major
__device__ __nv_bfloat16 g_al[(size_t)SEQ * BATCH * HID];  // A lo
__device__ __nv_bfloat16 g_wh[(size_t)G3 * HID];           // W hi [N][K] row-major
__device__ __nv_bfloat16 g_wl[(size_t)G3 * HID];           // W lo
__device__ unsigned g_count;
__device__ unsigned g_gen;

// ---------------------------------------------------------------------------
// fp32 -> (hi, lo) bf16 split.  Row m of src at (m>>5)*s0 + (m&31)*s1.
// ---------------------------------------------------------------------------
__global__ void conv_split(const float* __restrict__ src, int s0, int s1, int kbits,
                           size_t total, __nv_bfloat16* __restrict__ hi,
                           __nv_bfloat16* __restrict__ lo)
{
    const size_t km = ((size_t)1 << kbits) - 1;
    for (size_t idx = (size_t)blockIdx.x * blockDim.x + threadIdx.x; idx < total;
         idx += (size_t)gridDim.x * blockDim.x) {
        size_t m = idx >> kbits;
        int k = (int)(idx & km);
        float v = src[(m >> 5) * (size_t)s0 + (m & 31) * (size_t)s1 + k];
        __nv_bfloat16 h = __float2bfloat16(v);
        hi[idx] = h;
        lo[idx] = __float2bfloat16(v - __bfloat162float(h));
    }
}

// ---------------------------------------------------------------------------
// mma.sync split-bf16 GEMM (NT): C[m][n] = sum_k A[m][k]*W[n][k] + bias[n]
// C = Ah*Wh + Ah*Wl + Al*Wh.
// CTA 128x128, 8 warps (2m x 4n), warp tile 64x32, BK=32, cp.async double buf.
// C row offset = (m>>5)*c_s0 + (m&31)*c_s1.
// ---------------------------------------------------------------------------
#define TPAD 40                       // padded K stride (elements)
#define TILE_BYTES (128 * TPAD * 2)   // 10240
#define STAGE_BYTES (4 * TILE_BYTES)  // Ah, Al, Wh, Wl

__global__ __launch_bounds__(256)
void gemm_mma(const __nv_bfloat16* __restrict__ Ah, const __nv_bfloat16* __restrict__ Al,
              const __nv_bfloat16* __restrict__ Wh, const __nv_bfloat16* __restrict__ Wl,
              const float* __restrict__ bias, float* __restrict__ C,
              int K, int c_s0, int c_s1)
{
    extern __shared__ char smem[];
    const uint32_t sb = smem_u32(smem);

    const int tid  = threadIdx.x;
    const int wid  = tid >> 5;
    const int lane = tid & 31;
    const int wm   = wid >> 2;        // 0..1 (m)
    const int wn   = wid & 3;         // 0..3 (n)
    const int bm   = blockIdx.y * 128;
    const int bn   = blockIdx.x * 128;

    const __nv_bfloat16* srcs[4] = { Ah + (size_t)bm * K, Al + (size_t)bm * K,
                                     Wh + (size_t)bn * K, Wl + (size_t)bn * K };

    // per-thread load slots: 2 chunks (16B) per tile per stage
    const int c0 = tid;          // chunk 0..255
    const int c1 = tid + 256;    // chunk 256..511
    const int r0 = c0 >> 2, q0 = c0 & 3;
    const int r1 = c1 >> 2, q1 = c1 & 3;

    float acc[4][4][4];
#pragma unroll
    for (int m = 0; m < 4; m++)
#pragma unroll
        for (int n = 0; n < 4; n++)
#pragma unroll
            for (int v = 0; v < 4; v++) acc[m][n][v] = 0.f;

    const int KT = K >> 5;   // number of 32-wide k tiles

    // prologue: stage 0
#pragma unroll
    for (int t = 0; t < 4; t++) {
        const uint32_t db = sb + t * TILE_BYTES;
        CP16(db + r0 * (TPAD * 2) + q0 * 16, srcs[t] + (size_t)r0 * K + q0 * 8);
        CP16(db + r1 * (TPAD * 2) + q1 * 16, srcs[t] + (size_t)r1 * K + q1 * 8);
    }
    CP_COMMIT();

    // ldmatrix address components (constant per thread)
    const int a_row = (lane & 15);
    const int a_colh = (lane >> 4) * 8;          // 0 or 8
    const int b_row = (lane & 7);
    const int b_colh = ((lane >> 3) & 1) * 8;    // 0 or 8 (lanes 16+ replicate)

    for (int kt = 0; kt < KT; kt++) {
        CP_WAIT0();
        __syncthreads();

        const uint32_t buf = sb + (kt & 1) * STAGE_BYTES;

        if (kt + 1 < KT) {
            const int k0 = (kt + 1) << 5;
            const uint32_t nb = sb + ((kt + 1) & 1) * STAGE_BYTES;
#pragma unroll
            for (int t = 0; t < 4; t++) {
                const uint32_t db = nb + t * TILE_BYTES;
                CP16(db + r0 * (TPAD * 2) + q0 * 16, srcs[t] + (size_t)r0 * K + k0 + q0 * 8);
                CP16(db + r1 * (TPAD * 2) + q1 * 16, srcs[t] + (size_t)r1 * K + k0 + q1 * 8);
            }
            CP_COMMIT();
        }

#pragma unroll
        for (int k16 = 0; k16 < 2; k16++) {
            uint32_t ah4[4][4], al4[4][4], bh2[4][2], bl2[4][2];
#pragma unroll
            for (int m = 0; m < 4; m++) {
                const uint32_t arow = wm * 64 + m * 16 + a_row;
                const uint32_t acol = k16 * 16 + a_colh;
                const uint32_t aoff = arow * (TPAD * 2) + acol * 2;
                LDSM_X4(ah4[m][0], ah4[m][1], ah4[m][2], ah4[m][3], buf + 0 * TILE_BYTES + aoff);
                LDSM_X4(al4[m][0], al4[m][1], al4[m][2], al4[m][3], buf + 1 * TILE_BYTES + aoff);
            }
#pragma unroll
            for (int n = 0; n < 4; n++) {
                const uint32_t brow = wn * 32 + n * 8 + b_row;
                const uint32_t bcol = k16 * 16 + b_colh;
                const uint32_t boff = brow * (TPAD * 2) + bcol * 2;
                LDSM_X2(bh2[n][0], bh2[n][1], buf + 2 * TILE_BYTES + boff);
                LDSM_X2(bl2[n][0], bl2[n][1], buf + 3 * TILE_BYTES + boff);
            }
#pragma unroll
            for (int m = 0; m < 4; m++)
#pragma unroll
                for (int n = 0; n < 4; n++) {
                    MMA_BF16(acc[m][n], ah4[m], bh2[n]);
                    MMA_BF16(acc[m][n], ah4[m], bl2[n]);
                    MMA_BF16(acc[m][n], al4[m], bh2[n]);
                }
        }
        __syncthreads();
    }

    // epilogue: acc frag (m,n): rows bm+wm*64+m*16+{qid, qid+8}, cols bn+wn*32+n*8+qtr*2+{0,1}
    const int qid = lane >> 2;
    const int qtr = lane & 3;
#pragma unroll
    for (int m = 0; m < 4; m++) {
        const int ra = bm + wm * 64 + m * 16 + qid;
        const int rb = ra + 8;
        float* crowa = C + (size_t)(ra >> 5) * c_s0 + (size_t)(ra & 31) * c_s1;
        float* crowb = C + (size_t)(rb >> 5) * c_s0 + (size_t)(rb & 31) * c_s1;
#pragma unroll
        for (int n = 0; n < 4; n++) {
            const int col = bn + wn * 32 + n * 8 + qtr * 2;
            const float bv0 = bias[col], bv1 = bias[col + 1];
            float2 va, vb;
            va.x = acc[m][n][0] + bv0; va.y = acc[m][n][1] + bv1;
            vb.x = acc[m][n][2] + bv0; vb.y = acc[m][n][3] + bv1;
            *(float2*)(crowa + col) = va;
            *(float2*)(crowb + col) = vb;
        }
    }
}

// ---------------------------------------------------------------------------
// grid-wide barrier
// ---------------------------------------------------------------------------
__device__ __forceinline__ void grid_barrier()
{
    __syncthreads();
    if (threadIdx.x == 0) {
        unsigned old = *(volatile unsigned*)&g_gen;
        __threadfence();
        if (atomicAdd(&g_count, 1u) == NCTA - 1) {
            g_count = 0;
            __threadfence();
            atomicAdd(&g_gen, 1u);
        } else {
            while (*(volatile unsigned*)&g_gen == old) __nanosleep(64);
        }
        __threadfence();
    }
    __syncthreads();
}

// ---------------------------------------------------------------------------
// Persistent GRU layer scan (unchanged from passing version)
// ---------------------------------------------------------------------------
__global__ __launch_bounds__(256, 1)
void gru_scan(const float* __restrict__ gx, const float* __restrict__ Whh,
              const float* __restrict__ h0, float* __restrict__ y)
{
    extern __shared__ float smemf[];
    float4*     smh4 = (float4*)smemf;
    ulonglong2* smh2 = (ulonglong2*)smemf;
    float*      gxs  = smemf + 8192 * 4;

    const int tid = threadIdx.x;
    const int w   = tid >> 5;
    const int l   = tid & 31;
    const int lm  = l & 7;
    const int cta = blockIdx.x;
    const int j   = cta * 8 + w;

    ull wr[16], wz[16], wn[16];
    {
        const float* br = Whh + (size_t)j * HID + (size_t)l * 32;
        const float* bz = br + (size_t)HID * HID;
        const float* bn_ = bz + (size_t)HID * HID;
#pragma unroll
        for (int i = 0; i < 8; i++) {
            ulonglong2 u = *(const ulonglong2*)(br + i * 4);
            wr[2 * i] = u.x; wr[2 * i + 1] = u.y;
        }
#pragma unroll
        for (int i = 0; i < 8; i++) {
            ulonglong2 u = *(const ulonglong2*)(bz + i * 4);
            wz[2 * i] = u.x; wz[2 * i + 1] = u.y;
        }
#pragma unroll
        for (int i = 0; i < 8; i++) {
            ulonglong2 u = *(const ulonglong2*)(bn_ + i * 4);
            wn[2 * i] = u.x; wn[2 * i + 1] = u.y;
        }
    }

    int hoff[8];
#pragma unroll
    for (int i = 0; i < 8; i++) hoff[i] = l * 8 + (i ^ lm);
    const int sw_tid = tid ^ ((tid >> 3) & 7);

    for (int s = 0; s < SEQ; s++) {
        const float* hin = (s == 0) ? h0 : (y + (size_t)(s - 1) * (BATCH * HID));
        const float* gxsrc = gx + (size_t)s * (BATCH * G3);

#pragma unroll 8
        for (int b = 0; b < 32; b++) {
            float4 v = *(const float4*)(hin + (size_t)b * HID + tid * 4);
            smh4[b * 256 + sw_tid] = v;
        }
        if (tid < 192) {
            int bb = tid / 6, rem = tid % 6, g = rem >> 1, half = rem & 1;
            float4 v = *(const float4*)(gxsrc + (size_t)bb * G3 + g * HID + cta * 8 + half * 4);
            *(float4*)(gxs + bb * 28 + g * 8 + half * 4) = v;
        }
        const float hp = hin[(size_t)l * HID + j];
        __syncthreads();

        float myar = 0.f, myaz = 0.f, myan = 0.f;
#pragma unroll 2
        for (int b = 0; b < 32; b++) {
            ull ar = 0ull, az = 0ull, an = 0ull;
            const ulonglong2* hrow = smh2 + b * 256;
#pragma unroll
            for (int i = 0; i < 8; i++) {
                ulonglong2 h2 = hrow[hoff[i]];
                FMA2(ar, h2.x, wr[2 * i]); FMA2(ar, h2.y, wr[2 * i + 1]);
                FMA2(az, h2.x, wz[2 * i]); FMA2(az, h2.y, wz[2 * i + 1]);
                FMA2(an, h2.x, wn[2 * i]); FMA2(an, h2.y, wn[2 * i + 1]);
            }
            float sr = psum(ar), sz = psum(az), sn = psum(an);
#pragma unroll
            for (int off = 16; off; off >>= 1) {
                sr += __shfl_xor_sync(0xffffffffu, sr, off);
                sz += __shfl_xor_sync(0xffffffffu, sz, off);
                sn += __shfl_xor_sync(0xffffffffu, sn, off);
            }
            if (l == b) { myar = sr; myaz = sz; myan = sn; }
        }

        const float gxr = gxs[l * 28 + w];
        const float gxz = gxs[l * 28 + 8 + w];
        const float gxn = gxs[l * 28 + 16 + w];
        const float r = 1.f / (1.f + __expf(-(gxr + myar)));
        const float z = 1.f / (1.f + __expf(-(gxz + myaz)));
        const float npre = fmaf(r, myan, gxn + myan);
        const float e2 = __expf(2.f * npre);
        const float n = 1.f - 2.f / (e2 + 1.f);
        const float hnew = (1.f - z) * n + z * hp;
        y[(size_t)s * (BATCH * HID) + (size_t)l * HID + j] = hnew;

        __threadfence();
        grid_barrier();
    }
}

__global__ void copy_tail(const float* __restrict__ h0,
                          const float* __restrict__ h1,
                          float* __restrict__ dst)
{
    int i = blockIdx.x * blockDim.x + threadIdx.x;
    dst[i]               = h0[i];
    dst[BATCH * HID + i] = h1[i];
}

// ---------------------------------------------------------------------------
// kernel_launch
// ---------------------------------------------------------------------------
extern "C" void kernel_launch(void* const* d_in, const int* in_sizes, int n_in,
                              void* d_out, int out_size)
{
    const float* x    = (const float*)d_in[0];
    const float* Wih0 = (const float*)d_in[1];
    const float* Whh0 = (const float*)d_in[2];
    const float* b0   = (const float*)d_in[3];
    const float* Wih1 = (const float*)d_in[4];
    const float* Whh1 = (const float*)d_in[5];
    const float* b1   = (const float*)d_in[6];
    const float* Wlin = (const float*)d_in[7];
    const float* blin = (const float*)d_in[8];
    float* out = (float*)d_out;

    float *gx, *y0, *y1, *h0;
    __nv_bfloat16 *ah, *al, *wh, *wl;
    cudaGetSymbolAddress((void**)&gx, g_gx);
    cudaGetSymbolAddress((void**)&y0, g_y0);
    cudaGetSymbolAddress((void**)&y1, g_y1);
    cudaGetSymbolAddress((void**)&h0, g_h0);
    cudaGetSymbolAddress((void**)&ah, g_ah);
    cudaGetSymbolAddress((void**)&al, g_al);
    cudaGetSymbolAddress((void**)&wh, g_wh);
    cudaGetSymbolAddress((void**)&wl, g_wl);

    const int SCAN_SMEM = 8192 * 16 + 32 * 28 * 4;
    const int GEMM_SMEM = 2 * STAGE_BYTES;   // 81920
    cudaFuncSetAttribute(gru_scan, cudaFuncAttributeMaxDynamicSharedMemorySize, SCAN_SMEM);
    cudaFuncSetAttribute(gemm_mma, cudaFuncAttributeMaxDynamicSharedMemorySize, GEMM_SMEM);

    const int M = SEQ * BATCH;   // 16384

    // ---- layer 0 input GEMM: gx = x @ Wih0^T + b0 (time-major rows) ----
    conv_split<<<2048, 256>>>(x, IN_D, SEQ * IN_D, 9, (size_t)M * IN_D, ah, al);
    conv_split<<<2048, 256>>>(Wih0, 32 * IN_D, IN_D, 9, (size_t)G3 * IN_D, wh, wl);
    gemm_mma<<<dim3(G3 / 128, M / 128), 256, GEMM_SMEM>>>(
        ah, al, wh, wl, b0, gx, IN_D, 32 * G3, G3);

    gru_scan<<<NCTA, 256, SCAN_SMEM>>>(gx, Whh0, h0, y0);

    // ---- layer 1 input GEMM: gx = y0 @ Wih1^T + b1 ----
    conv_split<<<2048, 256>>>(y0, 32 * HID, HID, 10, (size_t)M * HID, ah, al);
    conv_split<<<2048, 256>>>(Wih1, 32 * HID, HID, 10, (size_t)G3 * HID, wh, wl);
    gemm_mma<<<dim3(G3 / 128, M / 128), 256, GEMM_SMEM>>>(
        ah, al, wh, wl, b1, gx, HID, 32 * G3, G3);

    gru_scan<<<NCTA, 256, SCAN_SMEM>>>(gx, Whh1, h0, y1);

    // ---- output GEMM: out[b][t][:] = y1 @ Wlin^T + blin ----
    conv_split<<<2048, 256>>>(y1, 32 * HID, HID, 10, (size_t)M * HID, ah, al);
    conv_split<<<2048, 256>>>(Wlin, 32 * HID, HID, 10, (size_t)IN_D * HID, wh, wl);
    gemm_mma<<<dim3(IN_D / 128, M / 128), 256, GEMM_SMEM>>>(
        ah, al, wh, wl, blin, out, HID, IN_D, SEQ * IN_D);

    copy_tail<<<128, 256>>>(y0 + (size_t)(SEQ - 1) * BATCH * HID,
                            y1 + (size_t)(SEQ - 1) * BATCH * HID,
                            out + (size_t)BATCH * SEQ * IN_D);
}

// round 7
// speedup vs baseline: 1.2737x; 1.1133x over previous
#include <cuda_runtime.h>
#include <cuda_bf16.h>
#include <math.h>
#include <stdint.h>

// Problem constants
#define BATCH 32
#define SEQ   512
#define IN_D  512
#define HID   1024
#define G3    3072   // 3*HID
#define NCTA  128    // persistent scan grid size

typedef unsigned long long ull;

__device__ __forceinline__ uint32_t smem_u32(const void* p) {
    uint32_t a;
    asm("{ .reg .u64 t; cvta.to.shared.u64 t, %1; cvt.u32.u64 %0, t; }" : "=r"(a) : "l"(p));
    return a;
}

// mma.sync / ldmatrix / cp.async (baseline ISA, works on sm_103 target)
#define LDSM_X4(r0, r1, r2, r3, addr) \
    asm volatile("ldmatrix.sync.aligned.m8n8.x4.shared.b16 {%0,%1,%2,%3}, [%4];" \
        : "=r"(r0), "=r"(r1), "=r"(r2), "=r"(r3) : "r"(addr))
#define LDSM_X2(r0, r1, addr) \
    asm volatile("ldmatrix.sync.aligned.m8n8.x2.shared.b16 {%0,%1}, [%2];" \
        : "=r"(r0), "=r"(r1) : "r"(addr))
#define MMA_BF16(d, a, b) \
    asm volatile("mma.sync.aligned.m16n8k16.row.col.f32.bf16.bf16.f32 " \
        "{%0,%1,%2,%3}, {%4,%5,%6,%7}, {%8,%9}, {%0,%1,%2,%3};" \
        : "+f"((d)[0]), "+f"((d)[1]), "+f"((d)[2]), "+f"((d)[3]) \
        : "r"((a)[0]), "r"((a)[1]), "r"((a)[2]), "r"((a)[3]), "r"((b)[0]), "r"((b)[1]))
#define CP16(dst, src) \
    asm volatile("cp.async.cg.shared.global [%0], [%1], 16;" :: "r"(dst), "l"(src))
#define CP_COMMIT() asm volatile("cp.async.commit_group;" ::: "memory")
#define CP_WAIT0()  asm volatile("cp.async.wait_group 0;" ::: "memory")
#define CP_WAIT1()  asm volatile("cp.async.wait_group 1;" ::: "memory")

// ---------------------------------------------------------------------------
// Scratch (device globals)
// ---------------------------------------------------------------------------
__device__ float g_gx[(size_t)SEQ * BATCH * G3];
__device__ float g_y0[(size_t)SEQ * BATCH * HID];
__device__ float g_y1[(size_t)SEQ * BATCH * HID];
__device__ __nv_bfloat16 g_ah[(size_t)SEQ * BATCH * HID];  // A hi [M][K] row-major
__device__ __nv_bfloat16 g_al[(size_t)SEQ * BATCH * HID];  // A lo
__device__ __nv_bfloat16 g_wh[(size_t)G3 * HID];           // W hi [N][K] row-major
__device__ __nv_bfloat16 g_wl[(size_t)G3 * HID];           // W lo
__device__ __nv_bfloat16 g_hb[2][64 * 512];                // h hi, double-buffered, chunked [ch][b][16]
__device__ __nv_bfloat16 g_hl[2][64 * 512];                // h lo
__device__ unsigned g_count;
__device__ unsigned g_gen;

// ---------------------------------------------------------------------------
// fp32 -> (hi, lo) bf16 split.  Row m of src at (m>>5)*s0 + (m&31)*s1.
// ---------------------------------------------------------------------------
__global__ void conv_split(const float* __restrict__ src, int s0, int s1, int kbits,
                           size_t total, __nv_bfloat16* __restrict__ hi,
                           __nv_bfloat16* __restrict__ lo)
{
    const size_t km = ((size_t)1 << kbits) - 1;
    for (size_t idx = (size_t)blockIdx.x * blockDim.x + threadIdx.x; idx < total;
         idx += (size_t)gridDim.x * blockDim.x) {
        size_t m = idx >> kbits;
        int k = (int)(idx & km);
        float v = src[(m >> 5) * (size_t)s0 + (m & 31) * (size_t)s1 + k];
        __nv_bfloat16 h = __float2bfloat16(v);
        hi[idx] = h;
        lo[idx] = __float2bfloat16(v - __bfloat162float(h));
    }
}

// ---------------------------------------------------------------------------
// mma.sync split-bf16 GEMM (NT) — unchanged from passing round 5
// ---------------------------------------------------------------------------
#define TPAD 40
#define TILE_BYTES (128 * TPAD * 2)
#define STAGE_BYTES (4 * TILE_BYTES)

__global__ __launch_bounds__(256)
void gemm_mma(const __nv_bfloat16* __restrict__ Ah, const __nv_bfloat16* __restrict__ Al,
              const __nv_bfloat16* __restrict__ Wh, const __nv_bfloat16* __restrict__ Wl,
              const float* __restrict__ bias, float* __restrict__ C,
              int K, int c_s0, int c_s1)
{
    extern __shared__ char smem[];
    const uint32_t sb = smem_u32(smem);

    const int tid  = threadIdx.x;
    const int wid  = tid >> 5;
    const int lane = tid & 31;
    const int wm   = wid >> 2;
    const int wn   = wid & 3;
    const int bm   = blockIdx.y * 128;
    const int bn   = blockIdx.x * 128;

    const __nv_bfloat16* srcs[4] = { Ah + (size_t)bm * K, Al + (size_t)bm * K,
                                     Wh + (size_t)bn * K, Wl + (size_t)bn * K };

    const int c0 = tid, c1 = tid + 256;
    const int r0 = c0 >> 2, q0 = c0 & 3;
    const int r1 = c1 >> 2, q1 = c1 & 3;

    float acc[4][4][4];
#pragma unroll
    for (int m = 0; m < 4; m++)
#pragma unroll
        for (int n = 0; n < 4; n++)
#pragma unroll
            for (int v = 0; v < 4; v++) acc[m][n][v] = 0.f;

    const int KT = K >> 5;

#pragma unroll
    for (int t = 0; t < 4; t++) {
        const uint32_t db = sb + t * TILE_BYTES;
        CP16(db + r0 * (TPAD * 2) + q0 * 16, srcs[t] + (size_t)r0 * K + q0 * 8);
        CP16(db + r1 * (TPAD * 2) + q1 * 16, srcs[t] + (size_t)r1 * K + q1 * 8);
    }
    CP_COMMIT();

    const int a_row = (lane & 15);
    const int a_colh = (lane >> 4) * 8;
    const int b_row = (lane & 7);
    const int b_colh = ((lane >> 3) & 1) * 8;

    for (int kt = 0; kt < KT; kt++) {
        CP_WAIT0();
        __syncthreads();

        const uint32_t buf = sb + (kt & 1) * STAGE_BYTES;

        if (kt + 1 < KT) {
            const int k0 = (kt + 1) << 5;
            const uint32_t nb = sb + ((kt + 1) & 1) * STAGE_BYTES;
#pragma unroll
            for (int t = 0; t < 4; t++) {
                const uint32_t db = nb + t * TILE_BYTES;
                CP16(db + r0 * (TPAD * 2) + q0 * 16, srcs[t] + (size_t)r0 * K + k0 + q0 * 8);
                CP16(db + r1 * (TPAD * 2) + q1 * 16, srcs[t] + (size_t)r1 * K + k0 + q1 * 8);
            }
            CP_COMMIT();
        }

#pragma unroll
        for (int k16 = 0; k16 < 2; k16++) {
            uint32_t ah4[4][4], al4[4][4], bh2[4][2], bl2[4][2];
#pragma unroll
            for (int m = 0; m < 4; m++) {
                const uint32_t arow = wm * 64 + m * 16 + a_row;
                const uint32_t acol = k16 * 16 + a_colh;
                const uint32_t aoff = arow * (TPAD * 2) + acol * 2;
                LDSM_X4(ah4[m][0], ah4[m][1], ah4[m][2], ah4[m][3], buf + 0 * TILE_BYTES + aoff);
                LDSM_X4(al4[m][0], al4[m][1], al4[m][2], al4[m][3], buf + 1 * TILE_BYTES + aoff);
            }
#pragma unroll
            for (int n = 0; n < 4; n++) {
                const uint32_t brow = wn * 32 + n * 8 + b_row;
                const uint32_t bcol = k16 * 16 + b_colh;
                const uint32_t boff = brow * (TPAD * 2) + bcol * 2;
                LDSM_X2(bh2[n][0], bh2[n][1], buf + 2 * TILE_BYTES + boff);
                LDSM_X2(bl2[n][0], bl2[n][1], buf + 3 * TILE_BYTES + boff);
            }
#pragma unroll
            for (int m = 0; m < 4; m++)
#pragma unroll
                for (int n = 0; n < 4; n++) {
                    MMA_BF16(acc[m][n], ah4[m], bh2[n]);
                    MMA_BF16(acc[m][n], ah4[m], bl2[n]);
                    MMA_BF16(acc[m][n], al4[m], bh2[n]);
                }
        }
        __syncthreads();
    }

    const int qid = lane >> 2;
    const int qtr = lane & 3;
#pragma unroll
    for (int m = 0; m < 4; m++) {
        const int ra = bm + wm * 64 + m * 16 + qid;
        const int rb = ra + 8;
        float* crowa = C + (size_t)(ra >> 5) * c_s0 + (size_t)(ra & 31) * c_s1;
        float* crowb = C + (size_t)(rb >> 5) * c_s0 + (size_t)(rb & 31) * c_s1;
#pragma unroll
        for (int n = 0; n < 4; n++) {
            const int col = bn + wn * 32 + n * 8 + qtr * 2;
            const float bv0 = bias[col], bv1 = bias[col + 1];
            float2 va, vb;
            va.x = acc[m][n][0] + bv0; va.y = acc[m][n][1] + bv1;
            vb.x = acc[m][n][2] + bv0; vb.y = acc[m][n][3] + bv1;
            *(float2*)(crowa + col) = va;
            *(float2*)(crowb + col) = vb;
        }
    }
}

// ---------------------------------------------------------------------------
// grid-wide barrier
// ---------------------------------------------------------------------------
__device__ __forceinline__ void grid_barrier()
{
    __syncthreads();
    if (threadIdx.x == 0) {
        unsigned old = *(volatile unsigned*)&g_gen;
        __threadfence();
        if (atomicAdd(&g_count, 1u) == NCTA - 1) {
            g_count = 0;
            __threadfence();
            atomicAdd(&g_gen, 1u);
        } else {
            while (*(volatile unsigned*)&g_gen == old) __nanosleep(32);
        }
        __threadfence();
    }
    __syncthreads();
}

// ---------------------------------------------------------------------------
// Persistent tensor-core GRU scan. 128 CTAs x 256 thr; CTA owns cols [c*8, c*8+8).
// Per step: gh[32 x 24] = h_split @ Whh_split^T (rows: r0-7 | z0-7 | n0-7 cols).
// Weights resident in SMEM (chunked [64][24][24] bf16, hi+lo). h broadcast via
// g_hb/g_hl DOUBLE-BUFFERED by step parity (step s reads buf[(s&1)^1], writes
// buf[s&1]) — removes the cross-CTA WAR race. cp.async pipelined in 8 k-blocks.
// Warps: (mi = wid>>2) m-half, (kq = wid&3) k-quarter -> SMEM reduction.
// ---------------------------------------------------------------------------
#define WS_BYTES  147456   // 2 splits * 64 ch * 24 rows * 24 elem * 2B
#define AB_BYTES  49152    // 2 buf * 2 splits * 8 ch * 32 * 24 * 2B
#define RED_BYTES 12288    // 8 warps * 16 * 24 fp32
#define GXS_BYTES 3072     // 32 * 24 fp32
#define SCAN_SMEM (WS_BYTES + AB_BYTES + RED_BYTES + GXS_BYTES)   // 211968

__global__ __launch_bounds__(256, 1)
void gru_scan_mma(const float* __restrict__ gx, const float* __restrict__ Whh,
                  float* __restrict__ y,
                  __nv_bfloat16* __restrict__ yh, __nv_bfloat16* __restrict__ yl,
                  __nv_bfloat16* __restrict__ hbg, __nv_bfloat16* __restrict__ hlg)
{
    extern __shared__ char sm[];
    __nv_bfloat16* ws = (__nv_bfloat16*)sm;
    float* red = (float*)(sm + WS_BYTES + AB_BYTES);
    float* gxs = (float*)(sm + WS_BYTES + AB_BYTES + RED_BYTES);
    const uint32_t sb   = smem_u32(sm);
    const uint32_t WS_B = sb;
    const uint32_t AB_B = sb + WS_BYTES;
    const uint32_t GX_B = sb + WS_BYTES + AB_BYTES + RED_BYTES;

    const int tid  = threadIdx.x;
    const int wid  = tid >> 5;
    const int lane = tid & 31;
    const int mi   = wid >> 2;    // m half (batch 0-15 / 16-31)
    const int kq   = wid & 3;     // k quarter
    const int cta  = blockIdx.x;
    const int eb   = tid >> 3;    // epilogue batch
    const int ejj  = tid & 7;     // epilogue col-in-cta
    const int ej   = cta * 8 + ejj;

    // ---- load + split Whh rows into SMEM (once) ----
    for (int i = tid; i < 24 * 1024; i += 256) {
        int r = i >> 10, k = i & 1023;
        int g = r >> 3, jj = r & 7;
        float v = Whh[((size_t)g * HID + cta * 8 + jj) * HID + k];
        __nv_bfloat16 h = __float2bfloat16(v);
        int off = (k >> 4) * 576 + r * 24 + (k & 15);
        ws[off] = h;
        ws[36864 + off] = __float2bfloat16(v - __bfloat162float(h));
    }
    __syncthreads();

    float hprev = 0.f;

    for (int s = 0; s < SEQ; s++) {
        // double-buffer selectors: read what step s-1 wrote; write for step s+1
        const __nv_bfloat16* hb_rd = hbg + (size_t)((s & 1) ^ 1) * (64 * 512);
        const __nv_bfloat16* hl_rd = hlg + (size_t)((s & 1) ^ 1) * (64 * 512);
        __nv_bfloat16* hb_wr = hbg + (size_t)(s & 1) * (64 * 512);
        __nv_bfloat16* hl_wr = hlg + (size_t)(s & 1) * (64 * 512);

        // prefetch gx slice [32 b][3 g][8 cols]
        if (tid < 192) {
            int b = tid / 6, rem = tid % 6, g = rem >> 1, half = rem & 1;
            CP16(GX_B + (uint32_t)(b * 24 + g * 8 + half * 4) * 4,
                 gx + (size_t)s * (BATCH * G3) + (size_t)b * G3 + g * HID + cta * 8 + half * 4);
        }

        float acc[3][4];
#pragma unroll
        for (int t3 = 0; t3 < 3; t3++)
#pragma unroll
            for (int v = 0; v < 4; v++) acc[t3][v] = 0.f;

        float gh0 = 0.f, gh1 = 0.f, gh2 = 0.f;

        if (s == 0) {
            CP_COMMIT(); CP_WAIT0(); __syncthreads();
            // h_prev = 0 -> gh = 0; skip mma entirely
        } else {
            // issue block 0 (+ gx already in this group)
#pragma unroll
            for (int it = 0; it < 4; it++) {
                int i = tid + it * 256;
                int split = i >> 9, rem = i & 511;
                int chL = rem >> 6, b2 = (rem >> 1) & 31, half = rem & 1;
                const __nv_bfloat16* src = (split ? hl_rd : hb_rd) + (size_t)chL * 512 + b2 * 16 + half * 8;
                CP16(AB_B + 2u * (split * 6144 + chL * 768 + b2 * 24 + half * 8), src);
            }
            CP_COMMIT();

            for (int blk = 0; blk < 8; blk++) {
                if (blk + 1 < 8) {
                    const int nbuf = (blk + 1) & 1;
#pragma unroll
                    for (int it = 0; it < 4; it++) {
                        int i = tid + it * 256;
                        int split = i >> 9, rem = i & 511;
                        int chL = rem >> 6, b2 = (rem >> 1) & 31, half = rem & 1;
                        const __nv_bfloat16* src = (split ? hl_rd : hb_rd) +
                            (size_t)((blk + 1) * 8 + chL) * 512 + b2 * 16 + half * 8;
                        CP16(AB_B + 2u * (nbuf * 12288 + split * 6144 + chL * 768 + b2 * 24 + half * 8), src);
                    }
                    CP_COMMIT();
                    CP_WAIT1();
                } else {
                    CP_WAIT0();
                }
                __syncthreads();

                const int buf = blk & 1;
#pragma unroll
                for (int cc2 = 0; cc2 < 2; cc2++) {
                    const int chL = kq + cc2 * 4;
                    const int ch  = blk * 8 + chL;
                    uint32_t aH[4], aL[4];
                    const uint32_t abase = AB_B + 2u * (buf * 12288 + chL * 768 +
                                         (mi * 16 + (lane & 15)) * 24 + (lane >> 4) * 8);
                    LDSM_X4(aH[0], aH[1], aH[2], aH[3], abase);
                    LDSM_X4(aL[0], aL[1], aL[2], aL[3], abase + 2u * 6144);
#pragma unroll
                    for (int t3 = 0; t3 < 3; t3++) {
                        uint32_t bH[2], bL[2];
                        const uint32_t bbase = WS_B + 2u * (ch * 576 +
                                             (t3 * 8 + (lane & 7)) * 24 + ((lane >> 3) & 1) * 8);
                        LDSM_X2(bH[0], bH[1], bbase);
                        LDSM_X2(bL[0], bL[1], bbase + 2u * 36864);
                        MMA_BF16(acc[t3], aH, bH);
                        MMA_BF16(acc[t3], aH, bL);
                        MMA_BF16(acc[t3], aL, bH);
                    }
                }
                __syncthreads();
            }

            // cross-warp k reduction via SMEM
#pragma unroll
            for (int t3 = 0; t3 < 3; t3++) {
                float* rp = red + wid * 384 + (lane >> 2) * 24 + t3 * 8 + (lane & 3) * 2;
                *(float2*)rp = make_float2(acc[t3][0], acc[t3][1]);
                *(float2*)(rp + 8 * 24) = make_float2(acc[t3][2], acc[t3][3]);
            }
            __syncthreads();

            const int mih = eb >> 4, rb = eb & 15;
#pragma unroll
            for (int q = 0; q < 4; q++) {
                const float* rp = red + (mih * 4 + q) * 384 + rb * 24;
                gh0 += rp[ejj];
                gh1 += rp[8 + ejj];
                gh2 += rp[16 + ejj];
            }
        }

        // gate update for (b=eb, j=ej)
        const float gxr = gxs[eb * 24 + ejj];
        const float gxz = gxs[eb * 24 + 8 + ejj];
        const float gxn = gxs[eb * 24 + 16 + ejj];
        const float r = 1.f / (1.f + __expf(-(gxr + gh0)));
        const float z = 1.f / (1.f + __expf(-(gxz + gh1)));
        const float npre = fmaf(r, gh2, gxn + gh2);
        const float e2 = __expf(2.f * npre);
        const float n = 1.f - 2.f / (e2 + 1.f);
        const float hnew = (1.f - z) * n + z * hprev;
        hprev = hnew;

        // stores: fp32 history, row-major bf16 splits (GEMM A), chunked broadcast
        y[(size_t)s * (BATCH * HID) + (size_t)eb * HID + ej] = hnew;
        const __nv_bfloat16 hh = __float2bfloat16(hnew);
        const __nv_bfloat16 hl = __float2bfloat16(hnew - __bfloat162float(hh));
        const size_t mrow = ((size_t)s * 32 + eb) * HID + ej;
        yh[mrow] = hh;
        yl[mrow] = hl;
        const int bidx = (ej >> 4) * 512 + eb * 16 + (ej & 15);
        hb_wr[bidx] = hh;
        hl_wr[bidx] = hl;

        __threadfence();   // release this thread's stores before barrier signal
        grid_barrier();
    }
}

// ---------------------------------------------------------------------------
// Tail: new_hidden = stack([h_last0, h_last1])
// ---------------------------------------------------------------------------
__global__ void copy_tail(const float* __restrict__ h0,
                          const float* __restrict__ h1,
                          float* __restrict__ dst)
{
    int i = blockIdx.x * blockDim.x + threadIdx.x;
    dst[i]               = h0[i];
    dst[BATCH * HID + i] = h1[i];
}

// ---------------------------------------------------------------------------
// kernel_launch
// ---------------------------------------------------------------------------
extern "C" void kernel_launch(void* const* d_in, const int* in_sizes, int n_in,
                              void* d_out, int out_size)
{
    const float* x    = (const float*)d_in[0];
    const float* Wih0 = (const float*)d_in[1];
    const float* Whh0 = (const float*)d_in[2];
    const float* b0   = (const float*)d_in[3];
    const float* Wih1 = (const float*)d_in[4];
    const float* Whh1 = (const float*)d_in[5];
    const float* b1   = (const float*)d_in[6];
    const float* Wlin = (const float*)d_in[7];
    const float* blin = (const float*)d_in[8];
    float* out = (float*)d_out;

    float *gx, *y0, *y1;
    __nv_bfloat16 *ah, *al, *wh, *wl, *hb, *hl;
    cudaGetSymbolAddress((void**)&gx, g_gx);
    cudaGetSymbolAddress((void**)&y0, g_y0);
    cudaGetSymbolAddress((void**)&y1, g_y1);
    cudaGetSymbolAddress((void**)&ah, g_ah);
    cudaGetSymbolAddress((void**)&al, g_al);
    cudaGetSymbolAddress((void**)&wh, g_wh);
    cudaGetSymbolAddress((void**)&wl, g_wl);
    cudaGetSymbolAddress((void**)&hb, g_hb);
    cudaGetSymbolAddress((void**)&hl, g_hl);

    const int GEMM_SMEM = 2 * STAGE_BYTES;
    cudaFuncSetAttribute(gemm_mma, cudaFuncAttributeMaxDynamicSharedMemorySize, GEMM_SMEM);
    cudaFuncSetAttribute(gru_scan_mma, cudaFuncAttributeMaxDynamicSharedMemorySize, SCAN_SMEM);

    const int M = SEQ * BATCH;   // 16384

    // ---- layer 0 input GEMM: gx = x @ Wih0^T + b0 (time-major rows) ----
    conv_split<<<2048, 256>>>(x, IN_D, SEQ * IN_D, 9, (size_t)M * IN_D, ah, al);
    conv_split<<<2048, 256>>>(Wih0, 32 * IN_D, IN_D, 9, (size_t)G3 * IN_D, wh, wl);
    gemm_mma<<<dim3(G3 / 128, M / 128), 256, GEMM_SMEM>>>(
        ah, al, wh, wl, b0, gx, IN_D, 32 * G3, G3);

    // ---- layer-0 scan (writes y0 fp32 + ah/al bf16 splits) ----
    gru_scan_mma<<<NCTA, 256, SCAN_SMEM>>>(gx, Whh0, y0, ah, al, hb, hl);

    // ---- layer 1 input GEMM: gx = y0 @ Wih1^T + b1 (A splits from scan) ----
    conv_split<<<2048, 256>>>(Wih1, 32 * HID, HID, 10, (size_t)G3 * HID, wh, wl);
    gemm_mma<<<dim3(G3 / 128, M / 128), 256, GEMM_SMEM>>>(
        ah, al, wh, wl, b1, gx, HID, 32 * G3, G3);

    // ---- layer-1 scan (overwrites ah/al with y1 splits) ----
    gru_scan_mma<<<NCTA, 256, SCAN_SMEM>>>(gx, Whh1, y1, ah, al, hb, hl);

    // ---- output GEMM: out[b][t][:] = y1 @ Wlin^T + blin ----
    conv_split<<<2048, 256>>>(Wlin, 32 * HID, HID, 10, (size_t)IN_D * HID, wh, wl);
    gemm_mma<<<dim3(IN_D / 128, M / 128), 256, GEMM_SMEM>>>(
        ah, al, wh, wl, blin, out, HID, IN_D, SEQ * IN_D);

    copy_tail<<<128, 256>>>(y0 + (size_t)(SEQ - 1) * BATCH * HID,
                            y1 + (size_t)(SEQ - 1) * BATCH * HID,
                            out + (size_t)BATCH * SEQ * IN_D);
}

// round 8
// speedup vs baseline: 1.4342x; 1.1261x over previous
#include <cuda_runtime.h>
#include <cuda_bf16.h>
#include <math.h>
#include <stdint.h>

// Problem constants
#define BATCH 32
#define SEQ   512
#define IN_D  512
#define HID   1024
#define G3    3072   // 3*HID
#define NCTA  128    // persistent scan grid size

typedef unsigned long long ull;

__device__ __forceinline__ uint32_t smem_u32(const void* p) {
    uint32_t a;
    asm("{ .reg .u64 t; cvta.to.shared.u64 t, %1; cvt.u32.u64 %0, t; }" : "=r"(a) : "l"(p));
    return a;
}

// mma.sync / ldmatrix / cp.async (baseline ISA, works on sm_103 target)
#define LDSM_X4(r0, r1, r2, r3, addr) \
    asm volatile("ldmatrix.sync.aligned.m8n8.x4.shared.b16 {%0,%1,%2,%3}, [%4];" \
        : "=r"(r0), "=r"(r1), "=r"(r2), "=r"(r3) : "r"(addr))
#define LDSM_X2(r0, r1, addr) \
    asm volatile("ldmatrix.sync.aligned.m8n8.x2.shared.b16 {%0,%1}, [%2];" \
        : "=r"(r0), "=r"(r1) : "r"(addr))
#define MMA_BF16(d, a, b) \
    asm volatile("mma.sync.aligned.m16n8k16.row.col.f32.bf16.bf16.f32 " \
        "{%0,%1,%2,%3}, {%4,%5,%6,%7}, {%8,%9}, {%0,%1,%2,%3};" \
        : "+f"((d)[0]), "+f"((d)[1]), "+f"((d)[2]), "+f"((d)[3]) \
        : "r"((a)[0]), "r"((a)[1]), "r"((a)[2]), "r"((a)[3]), "r"((b)[0]), "r"((b)[1]))
#define CP16(dst, src) \
    asm volatile("cp.async.cg.shared.global [%0], [%1], 16;" :: "r"(dst), "l"(src))
#define CP_COMMIT() asm volatile("cp.async.commit_group;" ::: "memory")
#define CP_WAIT0()  asm volatile("cp.async.wait_group 0;" ::: "memory")
#define CP_WAIT1()  asm volatile("cp.async.wait_group 1;" ::: "memory")

// ---------------------------------------------------------------------------
// Scratch (device globals)
// ---------------------------------------------------------------------------
__device__ float g_gx[(size_t)SEQ * BATCH * G3];
__device__ float g_y0[(size_t)SEQ * BATCH * HID];
__device__ float g_y1[(size_t)SEQ * BATCH * HID];
__device__ __nv_bfloat16 g_ah[(size_t)SEQ * BATCH * HID];  // A hi [M][K] row-major
__device__ __nv_bfloat16 g_al[(size_t)SEQ * BATCH * HID];  // A lo
__device__ __nv_bfloat16 g_wh[(size_t)G3 * HID];           // W hi [N][K] row-major
__device__ __nv_bfloat16 g_wl[(size_t)G3 * HID];           // W lo
__device__ __nv_bfloat16 g_hb[2][64 * 512];                // h hi, double-buffered, chunked [ch][b][16]
__device__ __nv_bfloat16 g_hl[2][64 * 512];                // h lo
__device__ unsigned g_count;
__device__ unsigned g_gen;

// ---------------------------------------------------------------------------
// fp32 -> (hi, lo) bf16 split.  Row m of src at (m>>5)*s0 + (m&31)*s1.
// ---------------------------------------------------------------------------
__global__ void conv_split(const float* __restrict__ src, int s0, int s1, int kbits,
                           size_t total, __nv_bfloat16* __restrict__ hi,
                           __nv_bfloat16* __restrict__ lo)
{
    const size_t km = ((size_t)1 << kbits) - 1;
    for (size_t idx = (size_t)blockIdx.x * blockDim.x + threadIdx.x; idx < total;
         idx += (size_t)gridDim.x * blockDim.x) {
        size_t m = idx >> kbits;
        int k = (int)(idx & km);
        float v = src[(m >> 5) * (size_t)s0 + (m & 31) * (size_t)s1 + k];
        __nv_bfloat16 h = __float2bfloat16(v);
        hi[idx] = h;
        lo[idx] = __float2bfloat16(v - __bfloat162float(h));
    }
}

// ---------------------------------------------------------------------------
// mma.sync split-bf16 GEMM (NT) — unchanged from passing round 5/7
// ---------------------------------------------------------------------------
#define TPAD 40
#define TILE_BYTES (128 * TPAD * 2)
#define STAGE_BYTES (4 * TILE_BYTES)

__global__ __launch_bounds__(256)
void gemm_mma(const __nv_bfloat16* __restrict__ Ah, const __nv_bfloat16* __restrict__ Al,
              const __nv_bfloat16* __restrict__ Wh, const __nv_bfloat16* __restrict__ Wl,
              const float* __restrict__ bias, float* __restrict__ C,
              int K, int c_s0, int c_s1)
{
    extern __shared__ char smem[];
    const uint32_t sb = smem_u32(smem);

    const int tid  = threadIdx.x;
    const int wid  = tid >> 5;
    const int lane = tid & 31;
    const int wm   = wid >> 2;
    const int wn   = wid & 3;
    const int bm   = blockIdx.y * 128;
    const int bn   = blockIdx.x * 128;

    const __nv_bfloat16* srcs[4] = { Ah + (size_t)bm * K, Al + (size_t)bm * K,
                                     Wh + (size_t)bn * K, Wl + (size_t)bn * K };

    const int c0 = tid, c1 = tid + 256;
    const int r0 = c0 >> 2, q0 = c0 & 3;
    const int r1 = c1 >> 2, q1 = c1 & 3;

    float acc[4][4][4];
#pragma unroll
    for (int m = 0; m < 4; m++)
#pragma unroll
        for (int n = 0; n < 4; n++)
#pragma unroll
            for (int v = 0; v < 4; v++) acc[m][n][v] = 0.f;

    const int KT = K >> 5;

#pragma unroll
    for (int t = 0; t < 4; t++) {
        const uint32_t db = sb + t * TILE_BYTES;
        CP16(db + r0 * (TPAD * 2) + q0 * 16, srcs[t] + (size_t)r0 * K + q0 * 8);
        CP16(db + r1 * (TPAD * 2) + q1 * 16, srcs[t] + (size_t)r1 * K + q1 * 8);
    }
    CP_COMMIT();

    const int a_row = (lane & 15);
    const int a_colh = (lane >> 4) * 8;
    const int b_row = (lane & 7);
    const int b_colh = ((lane >> 3) & 1) * 8;

    for (int kt = 0; kt < KT; kt++) {
        CP_WAIT0();
        __syncthreads();

        const uint32_t buf = sb + (kt & 1) * STAGE_BYTES;

        if (kt + 1 < KT) {
            const int k0 = (kt + 1) << 5;
            const uint32_t nb = sb + ((kt + 1) & 1) * STAGE_BYTES;
#pragma unroll
            for (int t = 0; t < 4; t++) {
                const uint32_t db = nb + t * TILE_BYTES;
                CP16(db + r0 * (TPAD * 2) + q0 * 16, srcs[t] + (size_t)r0 * K + k0 + q0 * 8);
                CP16(db + r1 * (TPAD * 2) + q1 * 16, srcs[t] + (size_t)r1 * K + k0 + q1 * 8);
            }
            CP_COMMIT();
        }

#pragma unroll
        for (int k16 = 0; k16 < 2; k16++) {
            uint32_t ah4[4][4], al4[4][4], bh2[4][2], bl2[4][2];
#pragma unroll
            for (int m = 0; m < 4; m++) {
                const uint32_t arow = wm * 64 + m * 16 + a_row;
                const uint32_t acol = k16 * 16 + a_colh;
                const uint32_t aoff = arow * (TPAD * 2) + acol * 2;
                LDSM_X4(ah4[m][0], ah4[m][1], ah4[m][2], ah4[m][3], buf + 0 * TILE_BYTES + aoff);
                LDSM_X4(al4[m][0], al4[m][1], al4[m][2], al4[m][3], buf + 1 * TILE_BYTES + aoff);
            }
#pragma unroll
            for (int n = 0; n < 4; n++) {
                const uint32_t brow = wn * 32 + n * 8 + b_row;
                const uint32_t bcol = k16 * 16 + b_colh;
                const uint32_t boff = brow * (TPAD * 2) + bcol * 2;
                LDSM_X2(bh2[n][0], bh2[n][1], buf + 2 * TILE_BYTES + boff);
                LDSM_X2(bl2[n][0], bl2[n][1], buf + 3 * TILE_BYTES + boff);
            }
#pragma unroll
            for (int m = 0; m < 4; m++)
#pragma unroll
                for (int n = 0; n < 4; n++) {
                    MMA_BF16(acc[m][n], ah4[m], bh2[n]);
                    MMA_BF16(acc[m][n], ah4[m], bl2[n]);
                    MMA_BF16(acc[m][n], al4[m], bh2[n]);
                }
        }
        __syncthreads();
    }

    const int qid = lane >> 2;
    const int qtr = lane & 3;
#pragma unroll
    for (int m = 0; m < 4; m++) {
        const int ra = bm + wm * 64 + m * 16 + qid;
        const int rb = ra + 8;
        float* crowa = C + (size_t)(ra >> 5) * c_s0 + (size_t)(ra & 31) * c_s1;
        float* crowb = C + (size_t)(rb >> 5) * c_s0 + (size_t)(rb & 31) * c_s1;
#pragma unroll
        for (int n = 0; n < 4; n++) {
            const int col = bn + wn * 32 + n * 8 + qtr * 2;
            const float bv0 = bias[col], bv1 = bias[col + 1];
            float2 va, vb;
            va.x = acc[m][n][0] + bv0; va.y = acc[m][n][1] + bv1;
            vb.x = acc[m][n][2] + bv0; vb.y = acc[m][n][3] + bv1;
            *(float2*)(crowa + col) = va;
            *(float2*)(crowb + col) = vb;
        }
    }
}

// ---------------------------------------------------------------------------
// grid-wide barrier — CG-style: bar.sync, tid0 fence+atomic, TIGHT spin
// (no nanosleep). Release/acquire chain: producers' stores -> bar.sync ->
// tid0 __threadfence -> atomic count -> last CTA fence -> gen bump ->
// waiter volatile read -> fence -> bar.sync -> consumers.
// ---------------------------------------------------------------------------
__device__ __forceinline__ void grid_barrier()
{
    __syncthreads();
    if (threadIdx.x == 0) {
        unsigned old = *(volatile unsigned*)&g_gen;
        __threadfence();
        if (atomicAdd(&g_count, 1u) == NCTA - 1) {
            g_count = 0;
            __threadfence();
            atomicAdd(&g_gen, 1u);
        } else {
            while (*(volatile unsigned*)&g_gen == old) { }
        }
        __threadfence();
    }
    __syncthreads();
}

// ---------------------------------------------------------------------------
// Persistent tensor-core GRU scan, v2 (latency-trimmed).
// 128 CTAs x 256 thr; CTA owns cols [c*8, c*8+8).
// Weights resident in SMEM, UNPADDED [64 ch][24 rows][16] with 16B-chunk XOR
// swizzle (half ^= (row>>2)&1) -> conflict-free ldmatrix. h broadcast double-
// buffered by step parity; cp.async pipeline of 4 blocks x 16 chunks.
// ---------------------------------------------------------------------------
#define WS_BYTES  98304    // 2 splits * 64 ch * 24 rows * 16 elem * 2B
#define AB_BYTES  98304    // 2 buf * 2 splits * 16 ch * 32 * 24 * 2B
#define RED_BYTES 12288    // 8 warps * 16 * 24 fp32
#define GXS_BYTES 3072     // 32 * 24 fp32
#define SCAN_SMEM (WS_BYTES + AB_BYTES + RED_BYTES + GXS_BYTES)   // 211968

__global__ __launch_bounds__(256, 1)
void gru_scan_mma(const float* __restrict__ gx, const float* __restrict__ Whh,
                  float* __restrict__ y,
                  __nv_bfloat16* __restrict__ yh, __nv_bfloat16* __restrict__ yl,
                  __nv_bfloat16* __restrict__ hbg, __nv_bfloat16* __restrict__ hlg)
{
    extern __shared__ char sm[];
    __nv_bfloat16* ws = (__nv_bfloat16*)sm;
    float* red = (float*)(sm + WS_BYTES + AB_BYTES);
    float* gxs = (float*)(sm + WS_BYTES + AB_BYTES + RED_BYTES);
    const uint32_t sb   = smem_u32(sm);
    const uint32_t WS_B = sb;
    const uint32_t AB_B = sb + WS_BYTES;
    const uint32_t GX_B = sb + WS_BYTES + AB_BYTES + RED_BYTES;

    const int tid  = threadIdx.x;
    const int wid  = tid >> 5;
    const int lane = tid & 31;
    const int mi   = wid >> 2;    // m half (batch 0-15 / 16-31)
    const int kq   = wid & 3;     // k quarter
    const int cta  = blockIdx.x;
    const int eb   = tid >> 3;    // epilogue batch
    const int ejj  = tid & 7;     // epilogue col-in-cta
    const int ej   = cta * 8 + ejj;

    // ---- load + split Whh rows into SMEM (once), swizzled unpadded layout ----
    for (int i = tid; i < 24 * 1024; i += 256) {
        int r = i >> 10, k = i & 1023;
        int g = r >> 3, jj = r & 7;
        float v = Whh[((size_t)g * HID + cta * 8 + jj) * HID + k];
        __nv_bfloat16 h = __float2bfloat16(v);
        int e = k & 15;
        int off = (k >> 4) * 384 + r * 16 + (((e >> 3) ^ ((r >> 2) & 1)) * 8) + (e & 7);
        ws[off] = h;
        ws[24576 + off] = __float2bfloat16(v - __bfloat162float(h));
    }
    __syncthreads();

    float hprev = 0.f;

    for (int s = 0; s < SEQ; s++) {
        const __nv_bfloat16* hb_rd = hbg + (size_t)((s & 1) ^ 1) * (64 * 512);
        const __nv_bfloat16* hl_rd = hlg + (size_t)((s & 1) ^ 1) * (64 * 512);
        __nv_bfloat16* hb_wr = hbg + (size_t)(s & 1) * (64 * 512);
        __nv_bfloat16* hl_wr = hlg + (size_t)(s & 1) * (64 * 512);

        // prefetch gx slice [32 b][3 g][8 cols]
        if (tid < 192) {
            int b = tid / 6, rem = tid % 6, g = rem >> 1, half = rem & 1;
            CP16(GX_B + (uint32_t)(b * 24 + g * 8 + half * 4) * 4,
                 gx + (size_t)s * (BATCH * G3) + (size_t)b * G3 + g * HID + cta * 8 + half * 4);
        }

        float acc[3][4];
#pragma unroll
        for (int t3 = 0; t3 < 3; t3++)
#pragma unroll
            for (int v = 0; v < 4; v++) acc[t3][v] = 0.f;

        float gh0 = 0.f, gh1 = 0.f, gh2 = 0.f;

        if (s == 0) {
            CP_COMMIT(); CP_WAIT0(); __syncthreads();
            // h_prev = 0 -> gh = 0; skip mma entirely
        } else {
            // issue block 0 (16 chunks) — same commit group as gx
#pragma unroll
            for (int it = 0; it < 8; it++) {
                int i = tid + it * 256;
                int split = i >> 10, rem = i & 1023;
                int chL = rem >> 6, b2 = (rem >> 1) & 31, half = rem & 1;
                const __nv_bfloat16* src = (split ? hl_rd : hb_rd) + (size_t)chL * 512 + b2 * 16 + half * 8;
                CP16(AB_B + 2u * (split * 12288 + chL * 768 + b2 * 24 + half * 8), src);
            }
            CP_COMMIT();

            for (int blk = 0; blk < 4; blk++) {
                if (blk + 1 < 4) {
                    const int nbuf = (blk + 1) & 1;
#pragma unroll
                    for (int it = 0; it < 8; it++) {
                        int i = tid + it * 256;
                        int split = i >> 10, rem = i & 1023;
                        int chL = rem >> 6, b2 = (rem >> 1) & 31, half = rem & 1;
                        const __nv_bfloat16* src = (split ? hl_rd : hb_rd) +
                            (size_t)((blk + 1) * 16 + chL) * 512 + b2 * 16 + half * 8;
                        CP16(AB_B + 2u * (nbuf * 24576 + split * 12288 + chL * 768 + b2 * 24 + half * 8), src);
                    }
                    CP_COMMIT();
                    CP_WAIT1();
                } else {
                    CP_WAIT0();
                }
                __syncthreads();

                const int buf = blk & 1;
#pragma unroll
                for (int cc2 = 0; cc2 < 4; cc2++) {
                    const int chL = kq + cc2 * 4;
                    const int ch  = blk * 16 + chL;
                    uint32_t aH[4], aL[4];
                    const uint32_t abase = AB_B + 2u * (buf * 24576 + chL * 768 +
                                         (mi * 16 + (lane & 15)) * 24 + (lane >> 4) * 8);
                    LDSM_X4(aH[0], aH[1], aH[2], aH[3], abase);
                    LDSM_X4(aL[0], aL[1], aL[2], aL[3], abase + 2u * 12288);
#pragma unroll
                    for (int t3 = 0; t3 < 3; t3++) {
                        const int brow = t3 * 8 + (lane & 7);
                        const int bh = (lane >> 3) & 1;
                        uint32_t bH[2], bL[2];
                        const uint32_t bbase = WS_B + 2u * (ch * 384 + brow * 16 +
                                             ((bh ^ ((brow >> 2) & 1)) * 8));
                        LDSM_X2(bH[0], bH[1], bbase);
                        LDSM_X2(bL[0], bL[1], bbase + 2u * 24576);
                        MMA_BF16(acc[t3], aH, bH);
                        MMA_BF16(acc[t3], aH, bL);
                        MMA_BF16(acc[t3], aL, bH);
                    }
                }
                __syncthreads();
            }

            // cross-warp k reduction via SMEM
#pragma unroll
            for (int t3 = 0; t3 < 3; t3++) {
                float* rp = red + wid * 384 + (lane >> 2) * 24 + t3 * 8 + (lane & 3) * 2;
                *(float2*)rp = make_float2(acc[t3][0], acc[t3][1]);
                *(float2*)(rp + 8 * 24) = make_float2(acc[t3][2], acc[t3][3]);
            }
            __syncthreads();

            const int mih = eb >> 4, rb = eb & 15;
#pragma unroll
            for (int q = 0; q < 4; q++) {
                const float* rp = red + (mih * 4 + q) * 384 + rb * 24;
                gh0 += rp[ejj];
                gh1 += rp[8 + ejj];
                gh2 += rp[16 + ejj];
            }
        }

        // gate update for (b=eb, j=ej)
        const float gxr = gxs[eb * 24 + ejj];
        const float gxz = gxs[eb * 24 + 8 + ejj];
        const float gxn = gxs[eb * 24 + 16 + ejj];
        const float r = 1.f / (1.f + __expf(-(gxr + gh0)));
        const float z = 1.f / (1.f + __expf(-(gxz + gh1)));
        const float npre = fmaf(r, gh2, gxn + gh2);
        const float e2 = __expf(2.f * npre);
        const float n = 1.f - 2.f / (e2 + 1.f);
        const float hnew = (1.f - z) * n + z * hprev;
        hprev = hnew;

        // stores: bf16 splits (GEMM A) every step; chunked broadcast; fp32 only last step
        if (s == SEQ - 1)
            y[(size_t)eb * HID + ej] = hnew;   // y points at last-step slot (see launch)
        const __nv_bfloat16 hh = __float2bfloat16(hnew);
        const __nv_bfloat16 hl = __float2bfloat16(hnew - __bfloat162float(hh));
        const size_t mrow = ((size_t)s * 32 + eb) * HID + ej;
        yh[mrow] = hh;
        yl[mrow] = hl;
        const int bidx = (ej >> 4) * 512 + eb * 16 + (ej & 15);
        hb_wr[bidx] = hh;
        hl_wr[bidx] = hl;

        grid_barrier();
    }
}

// ---------------------------------------------------------------------------
// Tail: new_hidden = stack([h_last0, h_last1])
// ---------------------------------------------------------------------------
__global__ void copy_tail(const float* __restrict__ h0,
                          const float* __restrict__ h1,
                          float* __restrict__ dst)
{
    int i = blockIdx.x * blockDim.x + threadIdx.x;
    dst[i]               = h0[i];
    dst[BATCH * HID + i] = h1[i];
}

// ---------------------------------------------------------------------------
// kernel_launch
// ---------------------------------------------------------------------------
extern "C" void kernel_launch(void* const* d_in, const int* in_sizes, int n_in,
                              void* d_out, int out_size)
{
    const float* x    = (const float*)d_in[0];
    const float* Wih0 = (const float*)d_in[1];
    const float* Whh0 = (const float*)d_in[2];
    const float* b0   = (const float*)d_in[3];
    const float* Wih1 = (const float*)d_in[4];
    const float* Whh1 = (const float*)d_in[5];
    const float* b1   = (const float*)d_in[6];
    const float* Wlin = (const float*)d_in[7];
    const float* blin = (const float*)d_in[8];
    float* out = (float*)d_out;

    float *gx, *y0, *y1;
    __nv_bfloat16 *ah, *al, *wh, *wl, *hb, *hl;
    cudaGetSymbolAddress((void**)&gx, g_gx);
    cudaGetSymbolAddress((void**)&y0, g_y0);
    cudaGetSymbolAddress((void**)&y1, g_y1);
    cudaGetSymbolAddress((void**)&ah, g_ah);
    cudaGetSymbolAddress((void**)&al, g_al);
    cudaGetSymbolAddress((void**)&wh, g_wh);
    cudaGetSymbolAddress((void**)&wl, g_wl);
    cudaGetSymbolAddress((void**)&hb, g_hb);
    cudaGetSymbolAddress((void**)&hl, g_hl);

    const int GEMM_SMEM = 2 * STAGE_BYTES;
    cudaFuncSetAttribute(gemm_mma, cudaFuncAttributeMaxDynamicSharedMemorySize, GEMM_SMEM);
    cudaFuncSetAttribute(gru_scan_mma, cudaFuncAttributeMaxDynamicSharedMemorySize, SCAN_SMEM);

    const int M = SEQ * BATCH;   // 16384

    // ---- layer 0 input GEMM: gx = x @ Wih0^T + b0 (time-major rows) ----
    conv_split<<<2048, 256>>>(x, IN_D, SEQ * IN_D, 9, (size_t)M * IN_D, ah, al);
    conv_split<<<2048, 256>>>(Wih0, 32 * IN_D, IN_D, 9, (size_t)G3 * IN_D, wh, wl);
    gemm_mma<<<dim3(G3 / 128, M / 128), 256, GEMM_SMEM>>>(
        ah, al, wh, wl, b0, gx, IN_D, 32 * G3, G3);

    // ---- layer-0 scan (y pointer = last-step slot only) ----
    gru_scan_mma<<<NCTA, 256, SCAN_SMEM>>>(gx, Whh0, y0, ah, al, hb, hl);

    // ---- layer 1 input GEMM: gx = y0 @ Wih1^T + b1 (A splits from scan) ----
    conv_split<<<2048, 256>>>(Wih1, 32 * HID, HID, 10, (size_t)G3 * HID, wh, wl);
    gemm_mma<<<dim3(G3 / 128, M / 128), 256, GEMM_SMEM>>>(
        ah, al, wh, wl, b1, gx, HID, 32 * G3, G3);

    // ---- layer-1 scan ----
    gru_scan_mma<<<NCTA, 256, SCAN_SMEM>>>(gx, Whh1, y1, ah, al, hb, hl);

    // ---- output GEMM: out[b][t][:] = y1 @ Wlin^T + blin ----
    conv_split<<<2048, 256>>>(Wlin, 32 * HID, HID, 10, (size_t)IN_D * HID, wh, wl);
    gemm_mma<<<dim3(IN_D / 128, M / 128), 256, GEMM_SMEM>>>(
        ah, al, wh, wl, blin, out, HID, IN_D, SEQ * IN_D);

    copy_tail<<<128, 256>>>(y0, y1, out + (size_t)BATCH * SEQ * IN_D);
}

// round 9
// speedup vs baseline: 2.0472x; 1.4274x over previous
#include <cuda_runtime.h>
#include <cuda_bf16.h>
#include <math.h>
#include <stdint.h>

// Problem constants
#define BATCH 32
#define SEQ   512
#define IN_D  512
#define HID   1024
#define G3    3072   // 3*HID
#define NCTA  128    // persistent scan grid size

typedef unsigned long long ull;

__device__ __forceinline__ uint32_t smem_u32(const void* p) {
    uint32_t a;
    asm("{ .reg .u64 t; cvta.to.shared.u64 t, %1; cvt.u32.u64 %0, t; }" : "=r"(a) : "l"(p));
    return a;
}

// mma.sync / ldmatrix / cp.async (baseline ISA, works on sm_103 target)
#define LDSM_X4(r0, r1, r2, r3, addr) \
    asm volatile("ldmatrix.sync.aligned.m8n8.x4.shared.b16 {%0,%1,%2,%3}, [%4];" \
        : "=r"(r0), "=r"(r1), "=r"(r2), "=r"(r3) : "r"(addr))
#define LDSM_X2(r0, r1, addr) \
    asm volatile("ldmatrix.sync.aligned.m8n8.x2.shared.b16 {%0,%1}, [%2];" \
        : "=r"(r0), "=r"(r1) : "r"(addr))
#define MMA_BF16(d, a, b) \
    asm volatile("mma.sync.aligned.m16n8k16.row.col.f32.bf16.bf16.f32 " \
        "{%0,%1,%2,%3}, {%4,%5,%6,%7}, {%8,%9}, {%0,%1,%2,%3};" \
        : "+f"((d)[0]), "+f"((d)[1]), "+f"((d)[2]), "+f"((d)[3]) \
        : "r"((a)[0]), "r"((a)[1]), "r"((a)[2]), "r"((a)[3]), "r"((b)[0]), "r"((b)[1]))
#define CP16(dst, src) \
    asm volatile("cp.async.cg.shared.global [%0], [%1], 16;" :: "r"(dst), "l"(src))
#define CP_COMMIT() asm volatile("cp.async.commit_group;" ::: "memory")
#define CP_WAIT0()  asm volatile("cp.async.wait_group 0;" ::: "memory")

// ---------------------------------------------------------------------------
// Scratch (device globals)
// ---------------------------------------------------------------------------
__device__ float g_gx[(size_t)SEQ * BATCH * G3];
__device__ float g_y0[(size_t)SEQ * BATCH * HID];
__device__ float g_y1[(size_t)SEQ * BATCH * HID];
__device__ __nv_bfloat16 g_ah[(size_t)SEQ * BATCH * HID];  // A hi [M][K] row-major
__device__ __nv_bfloat16 g_al[(size_t)SEQ * BATCH * HID];  // A lo
__device__ __nv_bfloat16 g_wh[(size_t)G3 * HID];           // W hi [N][K] row-major
__device__ __nv_bfloat16 g_wl[(size_t)G3 * HID];           // W lo
__device__ __align__(16) __nv_bfloat16 g_hb[2][64 * 512];  // h hi, double-buffered, chunked [ch][b][16]
__device__ __align__(16) __nv_bfloat16 g_hl[2][64 * 512];  // h lo

// hierarchical barrier state (zero-init; gens monotonic, counts self-reset)
__device__ unsigned g_gcnt[16 * 64];   // group counters, 256B apart
__device__ unsigned g_ggen[16 * 64];   // group generations, 256B apart
__device__ unsigned g_rcnt;
__device__ unsigned g_rgen;

// ---------------------------------------------------------------------------
// fp32 -> (hi, lo) bf16 split.  Row m of src at (m>>5)*s0 + (m&31)*s1.
// ---------------------------------------------------------------------------
__global__ void conv_split(const float* __restrict__ src, int s0, int s1, int kbits,
                           size_t total, __nv_bfloat16* __restrict__ hi,
                           __nv_bfloat16* __restrict__ lo)
{
    const size_t km = ((size_t)1 << kbits) - 1;
    for (size_t idx = (size_t)blockIdx.x * blockDim.x + threadIdx.x; idx < total;
         idx += (size_t)gridDim.x * blockDim.x) {
        size_t m = idx >> kbits;
        int k = (int)(idx & km);
        float v = src[(m >> 5) * (size_t)s0 + (m & 31) * (size_t)s1 + k];
        __nv_bfloat16 h = __float2bfloat16(v);
        hi[idx] = h;
        lo[idx] = __float2bfloat16(v - __bfloat162float(h));
    }
}

// ---------------------------------------------------------------------------
// mma.sync split-bf16 GEMM (NT) — unchanged from passing rounds 5/7/8
// ---------------------------------------------------------------------------
#define TPAD 40
#define TILE_BYTES (128 * TPAD * 2)
#define STAGE_BYTES (4 * TILE_BYTES)
#define CP_WAIT1()  asm volatile("cp.async.wait_group 1;" ::: "memory")

__global__ __launch_bounds__(256)
void gemm_mma(const __nv_bfloat16* __restrict__ Ah, const __nv_bfloat16* __restrict__ Al,
              const __nv_bfloat16* __restrict__ Wh, const __nv_bfloat16* __restrict__ Wl,
              const float* __restrict__ bias, float* __restrict__ C,
              int K, int c_s0, int c_s1)
{
    extern __shared__ char smem[];
    const uint32_t sb = smem_u32(smem);

    const int tid  = threadIdx.x;
    const int wid  = tid >> 5;
    const int lane = tid & 31;
    const int wm   = wid >> 2;
    const int wn   = wid & 3;
    const int bm   = blockIdx.y * 128;
    const int bn   = blockIdx.x * 128;

    const __nv_bfloat16* srcs[4] = { Ah + (size_t)bm * K, Al + (size_t)bm * K,
                                     Wh + (size_t)bn * K, Wl + (size_t)bn * K };

    const int c0 = tid, c1 = tid + 256;
    const int r0 = c0 >> 2, q0 = c0 & 3;
    const int r1 = c1 >> 2, q1 = c1 & 3;

    float acc[4][4][4];
#pragma unroll
    for (int m = 0; m < 4; m++)
#pragma unroll
        for (int n = 0; n < 4; n++)
#pragma unroll
            for (int v = 0; v < 4; v++) acc[m][n][v] = 0.f;

    const int KT = K >> 5;

#pragma unroll
    for (int t = 0; t < 4; t++) {
        const uint32_t db = sb + t * TILE_BYTES;
        CP16(db + r0 * (TPAD * 2) + q0 * 16, srcs[t] + (size_t)r0 * K + q0 * 8);
        CP16(db + r1 * (TPAD * 2) + q1 * 16, srcs[t] + (size_t)r1 * K + q1 * 8);
    }
    CP_COMMIT();

    const int a_row = (lane & 15);
    const int a_colh = (lane >> 4) * 8;
    const int b_row = (lane & 7);
    const int b_colh = ((lane >> 3) & 1) * 8;

    for (int kt = 0; kt < KT; kt++) {
        CP_WAIT0();
        __syncthreads();

        const uint32_t buf = sb + (kt & 1) * STAGE_BYTES;

        if (kt + 1 < KT) {
            const int k0 = (kt + 1) << 5;
            const uint32_t nb = sb + ((kt + 1) & 1) * STAGE_BYTES;
#pragma unroll
            for (int t = 0; t < 4; t++) {
                const uint32_t db = nb + t * TILE_BYTES;
                CP16(db + r0 * (TPAD * 2) + q0 * 16, srcs[t] + (size_t)r0 * K + k0 + q0 * 8);
                CP16(db + r1 * (TPAD * 2) + q1 * 16, srcs[t] + (size_t)r1 * K + k0 + q1 * 8);
            }
            CP_COMMIT();
        }

#pragma unroll
        for (int k16 = 0; k16 < 2; k16++) {
            uint32_t ah4[4][4], al4[4][4], bh2[4][2], bl2[4][2];
#pragma unroll
            for (int m = 0; m < 4; m++) {
                const uint32_t arow = wm * 64 + m * 16 + a_row;
                const uint32_t acol = k16 * 16 + a_colh;
                const uint32_t aoff = arow * (TPAD * 2) + acol * 2;
                LDSM_X4(ah4[m][0], ah4[m][1], ah4[m][2], ah4[m][3], buf + 0 * TILE_BYTES + aoff);
                LDSM_X4(al4[m][0], al4[m][1], al4[m][2], al4[m][3], buf + 1 * TILE_BYTES + aoff);
            }
#pragma unroll
            for (int n = 0; n < 4; n++) {
                const uint32_t brow = wn * 32 + n * 8 + b_row;
                const uint32_t bcol = k16 * 16 + b_colh;
                const uint32_t boff = brow * (TPAD * 2) + bcol * 2;
                LDSM_X2(bh2[n][0], bh2[n][1], buf + 2 * TILE_BYTES + boff);
                LDSM_X2(bl2[n][0], bl2[n][1], buf + 3 * TILE_BYTES + boff);
            }
#pragma unroll
            for (int m = 0; m < 4; m++)
#pragma unroll
                for (int n = 0; n < 4; n++) {
                    MMA_BF16(acc[m][n], ah4[m], bh2[n]);
                    MMA_BF16(acc[m][n], ah4[m], bl2[n]);
                    MMA_BF16(acc[m][n], al4[m], bh2[n]);
                }
        }
        __syncthreads();
    }

    const int qid = lane >> 2;
    const int qtr = lane & 3;
#pragma unroll
    for (int m = 0; m < 4; m++) {
        const int ra = bm + wm * 64 + m * 16 + qid;
        const int rb = ra + 8;
        float* crowa = C + (size_t)(ra >> 5) * c_s0 + (size_t)(ra & 31) * c_s1;
        float* crowb = C + (size_t)(rb >> 5) * c_s0 + (size_t)(rb & 31) * c_s1;
#pragma unroll
        for (int n = 0; n < 4; n++) {
            const int col = bn + wn * 32 + n * 8 + qtr * 2;
            const float bv0 = bias[col], bv1 = bias[col + 1];
            float2 va, vb;
            va.x = acc[m][n][0] + bv0; va.y = acc[m][n][1] + bv1;
            vb.x = acc[m][n][2] + bv0; vb.y = acc[m][n][3] + bv1;
            *(float2*)(crowa + col) = va;
            *(float2*)(crowb + col) = vb;
        }
    }
}

// ---------------------------------------------------------------------------
// grid-wide barrier — two-level tree: 16 groups x 8 CTAs, 16-way root.
// Cuts single-line atomic serialization ~5x. Same monotonic-gen + fence
// (cumulativity) scheme that passed R8.
// ---------------------------------------------------------------------------
__device__ __forceinline__ void grid_barrier()
{
    __syncthreads();
    if (threadIdx.x == 0) {
        const int g = blockIdx.x >> 3;          // 16 groups of 8
        volatile unsigned* ggen = g_ggen + g * 64;
        unsigned old = *ggen;
        __threadfence();
        if (atomicAdd(&g_gcnt[g * 64], 1u) == 7) {
            unsigned rold = *(volatile unsigned*)&g_rgen;
            if (atomicAdd(&g_rcnt, 1u) == 15) {
                g_rcnt = 0;
                __threadfence();
                atomicAdd(&g_rgen, 1u);
            } else {
                while (*(volatile unsigned*)&g_rgen == rold) { }
            }
            g_gcnt[g * 64] = 0;
            __threadfence();
            atomicAdd(&g_ggen[g * 64], 1u);
        } else {
            while (*ggen == old) { }
        }
        __threadfence();
    }
    __syncthreads();
}

// ---------------------------------------------------------------------------
// Persistent tensor-core GRU scan, v3 (one-shot staging).
// 128 CTAs x 256 thr; CTA owns cols [c*8, c*8+8).
// Weights resident in SMEM (XOR-swizzled unpadded, as R8). h staged in ONE
// cp.async batch per step into an unpadded XOR-swizzled A buffer (1KB/chunk,
// 128KB total, single-buffered). Reduction buffer ALIASES the A buffer
// (phase-disjoint). gx comes via 3 prefetched LDGs into registers.
// Syncs per step: wait+sync, mma-done sync, red sync, barrier.
// ---------------------------------------------------------------------------
#define WS_BYTES  98304    // 2 splits * 64 ch * 24 rows * 16 elem * 2B
#define AB_BYTES  131072   // 2 splits * 64 ch * 32 b * 16 elem * 2B (single buf)
#define SCAN_SMEM (WS_BYTES + AB_BYTES)   // 229376

__global__ __launch_bounds__(256, 1)
void gru_scan_mma(const float* __restrict__ gx, const float* __restrict__ Whh,
                  float* __restrict__ y,
                  __nv_bfloat16* __restrict__ yh, __nv_bfloat16* __restrict__ yl,
                  __nv_bfloat16* __restrict__ hbg, __nv_bfloat16* __restrict__ hlg)
{
    extern __shared__ char sm[];
    __nv_bfloat16* ws = (__nv_bfloat16*)sm;
    float* red = (float*)(sm + WS_BYTES);        // aliases A buffer (phase-disjoint)
    const uint32_t sb   = smem_u32(sm);
    const uint32_t WS_B = sb;
    const uint32_t AB_B = sb + WS_BYTES;

    const int tid  = threadIdx.x;
    const int wid  = tid >> 5;
    const int lane = tid & 31;
    const int mi   = wid >> 2;    // m half (batch 0-15 / 16-31)
    const int kq   = wid & 3;     // k quarter (16 chunks each)
    const int cta  = blockIdx.x;
    const int eb   = tid >> 3;    // epilogue batch
    const int ejj  = tid & 7;     // epilogue col-in-cta
    const int ej   = cta * 8 + ejj;

    // ---- load + split Whh rows into SMEM (once), XOR-swizzled unpadded ----
    for (int i = tid; i < 24 * 1024; i += 256) {
        int r = i >> 10, k = i & 1023;
        int g = r >> 3, jj = r & 7;
        float v = Whh[((size_t)g * HID + cta * 8 + jj) * HID + k];
        __nv_bfloat16 h = __float2bfloat16(v);
        int e = k & 15;
        int off = (k >> 4) * 384 + r * 16 + (((e >> 3) ^ ((r >> 2) & 1)) * 8) + (e & 7);
        ws[off] = h;
        ws[24576 + off] = __float2bfloat16(v - __bfloat162float(h));
    }
    __syncthreads();

    // per-lane constant A offset within a 1KB chunk (row = mi*16 + lane&15)
    const int a_row = mi * 16 + (lane & 15);
    const uint32_t a_off = (uint32_t)a_row * 32 +
                           ((((lane >> 4) ^ ((lane >> 2) & 1)) & 1) << 4);

    float hprev = 0.f;

    for (int s = 0; s < SEQ; s++) {
        // gx prefetch into registers (LDGs overlap the mma phase)
        const float* gp = gx + (size_t)s * (BATCH * G3) + (size_t)eb * G3 + cta * 8 + ejj;
        const float gxr = __ldg(gp);
        const float gxz = __ldg(gp + HID);
        const float gxn = __ldg(gp + 2 * HID);

        float gh0 = 0.f, gh1 = 0.f, gh2 = 0.f;

        if (s > 0) {
            const __nv_bfloat16* hb_rd = hbg + (size_t)((s & 1) ^ 1) * (64 * 512);
            const __nv_bfloat16* hl_rd = hlg + (size_t)((s & 1) ^ 1) * (64 * 512);

            // ONE cp.async batch: all 128 chunks (2 splits x 64), 32 CP16/thread
#pragma unroll
            for (int it = 0; it < 32; it++) {
                int i = tid + it * 256;
                int split = i >> 12, rem = i & 4095;
                int ch = rem >> 6, b = (rem >> 1) & 31, half = rem & 1;
                const __nv_bfloat16* src = (split ? hl_rd : hb_rd) +
                                           (size_t)ch * 512 + b * 16 + half * 8;
                uint32_t dst = AB_B + (uint32_t)split * 65536 + (uint32_t)ch * 1024 +
                               (uint32_t)b * 32 + (uint32_t)((half ^ ((b >> 2) & 1)) << 4);
                CP16(dst, src);
            }
            CP_COMMIT();
            CP_WAIT0();
            __syncthreads();

            float acc[3][4];
#pragma unroll
            for (int t3 = 0; t3 < 3; t3++)
#pragma unroll
                for (int v = 0; v < 4; v++) acc[t3][v] = 0.f;

#pragma unroll
            for (int i = 0; i < 16; i++) {
                const int ch = kq * 16 + i;
                const uint32_t ab = AB_B + (uint32_t)ch * 1024 + a_off;
                uint32_t aH[4], aL[4];
                LDSM_X4(aH[0], aH[1], aH[2], aH[3], ab);
                LDSM_X4(aL[0], aL[1], aL[2], aL[3], ab + 65536u);
#pragma unroll
                for (int t3 = 0; t3 < 3; t3++) {
                    const int brow = t3 * 8 + (lane & 7);
                    const int bh = (lane >> 3) & 1;
                    uint32_t bH[2], bL[2];
                    const uint32_t bbase = WS_B + 2u * (ch * 384 + brow * 16 +
                                         ((bh ^ ((brow >> 2) & 1)) * 8));
                    LDSM_X2(bH[0], bH[1], bbase);
                    LDSM_X2(bL[0], bL[1], bbase + 2u * 24576);
                    MMA_BF16(acc[t3], aH, bH);
                    MMA_BF16(acc[t3], aH, bL);
                    MMA_BF16(acc[t3], aL, bH);
                }
            }
            __syncthreads();   // mma done -> A buffer free for reduction alias

            // cross-warp k reduction via SMEM (aliases A buffer)
#pragma unroll
            for (int t3 = 0; t3 < 3; t3++) {
                float* rp = red + wid * 384 + (lane >> 2) * 24 + t3 * 8 + (lane & 3) * 2;
                *(float2*)rp = make_float2(acc[t3][0], acc[t3][1]);
                *(float2*)(rp + 8 * 24) = make_float2(acc[t3][2], acc[t3][3]);
            }
            __syncthreads();

            const int mih = eb >> 4, rb = eb & 15;
#pragma unroll
            for (int q = 0; q < 4; q++) {
                const float* rp = red + (mih * 4 + q) * 384 + rb * 24;
                gh0 += rp[ejj];
                gh1 += rp[8 + ejj];
                gh2 += rp[16 + ejj];
            }
        }

        // gate update for (b=eb, j=ej)
        const float r = 1.f / (1.f + __expf(-(gxr + gh0)));
        const float z = 1.f / (1.f + __expf(-(gxz + gh1)));
        const float npre = fmaf(r, gh2, gxn + gh2);
        const float e2 = __expf(2.f * npre);
        const float n = 1.f - 2.f / (e2 + 1.f);
        const float hnew = (1.f - z) * n + z * hprev;
        hprev = hnew;

        // stores: bf16 splits (GEMM A) every step; chunked broadcast; fp32 last step
        if (s == SEQ - 1)
            y[(size_t)eb * HID + ej] = hnew;
        const __nv_bfloat16 hh = __float2bfloat16(hnew);
        const __nv_bfloat16 hl = __float2bfloat16(hnew - __bfloat162float(hh));
        const size_t mrow = ((size_t)s * 32 + eb) * HID + ej;
        yh[mrow] = hh;
        yl[mrow] = hl;
        __nv_bfloat16* hb_wr = hbg + (size_t)(s & 1) * (64 * 512);
        __nv_bfloat16* hl_wr = hlg + (size_t)(s & 1) * (64 * 512);
        const int bidx = (ej >> 4) * 512 + eb * 16 + (ej & 15);
        hb_wr[bidx] = hh;
        hl_wr[bidx] = hl;

        grid_barrier();
    }
}

// ---------------------------------------------------------------------------
// Tail: new_hidden = stack([h_last0, h_last1])
// ---------------------------------------------------------------------------
__global__ void copy_tail(const float* __restrict__ h0,
                          const float* __restrict__ h1,
                          float* __restrict__ dst)
{
    int i = blockIdx.x * blockDim.x + threadIdx.x;
    dst[i]               = h0[i];
    dst[BATCH * HID + i] = h1[i];
}

// ---------------------------------------------------------------------------
// kernel_launch
// ---------------------------------------------------------------------------
extern "C" void kernel_launch(void* const* d_in, const int* in_sizes, int n_in,
                              void* d_out, int out_size)
{
    const float* x    = (const float*)d_in[0];
    const float* Wih0 = (const float*)d_in[1];
    const float* Whh0 = (const float*)d_in[2];
    const float* b0   = (const float*)d_in[3];
    const float* Wih1 = (const float*)d_in[4];
    const float* Whh1 = (const float*)d_in[5];
    const float* b1   = (const float*)d_in[6];
    const float* Wlin = (const float*)d_in[7];
    const float* blin = (const float*)d_in[8];
    float* out = (float*)d_out;

    float *gx, *y0, *y1;
    __nv_bfloat16 *ah, *al, *wh, *wl, *hb, *hl;
    cudaGetSymbolAddress((void**)&gx, g_gx);
    cudaGetSymbolAddress((void**)&y0, g_y0);
    cudaGetSymbolAddress((void**)&y1, g_y1);
    cudaGetSymbolAddress((void**)&ah, g_ah);
    cudaGetSymbolAddress((void**)&al, g_al);
    cudaGetSymbolAddress((void**)&wh, g_wh);
    cudaGetSymbolAddress((void**)&wl, g_wl);
    cudaGetSymbolAddress((void**)&hb, g_hb);
    cudaGetSymbolAddress((void**)&hl, g_hl);

    const int GEMM_SMEM = 2 * STAGE_BYTES;
    cudaFuncSetAttribute(gemm_mma, cudaFuncAttributeMaxDynamicSharedMemorySize, GEMM_SMEM);
    cudaFuncSetAttribute(gru_scan_mma, cudaFuncAttributeMaxDynamicSharedMemorySize, SCAN_SMEM);

    const int M = SEQ * BATCH;   // 16384

    // ---- layer 0 input GEMM: gx = x @ Wih0^T + b0 (time-major rows) ----
    conv_split<<<2048, 256>>>(x, IN_D, SEQ * IN_D, 9, (size_t)M * IN_D, ah, al);
    conv_split<<<2048, 256>>>(Wih0, 32 * IN_D, IN_D, 9, (size_t)G3 * IN_D, wh, wl);
    gemm_mma<<<dim3(G3 / 128, M / 128), 256, GEMM_SMEM>>>(
        ah, al, wh, wl, b0, gx, IN_D, 32 * G3, G3);

    // ---- layer-0 scan (y pointer = last-step slot only) ----
    gru_scan_mma<<<NCTA, 256, SCAN_SMEM>>>(gx, Whh0, y0, ah, al, hb, hl);

    // ---- layer 1 input GEMM: gx = y0 @ Wih1^T + b1 (A splits from scan) ----
    conv_split<<<2048, 256>>>(Wih1, 32 * HID, HID, 10, (size_t)G3 * HID, wh, wl);
    gemm_mma<<<dim3(G3 / 128, M / 128), 256, GEMM_SMEM>>>(
        ah, al, wh, wl, b1, gx, HID, 32 * G3, G3);

    // ---- layer-1 scan ----
    gru_scan_mma<<<NCTA, 256, SCAN_SMEM>>>(gx, Whh1, y1, ah, al, hb, hl);

    // ---- output GEMM: out[b][t][:] = y1 @ Wlin^T + blin ----
    conv_split<<<2048, 256>>>(Wlin, 32 * HID, HID, 10, (size_t)IN_D * HID, wh, wl);
    gemm_mma<<<dim3(IN_D / 128, M / 128), 256, GEMM_SMEM>>>(
        ah, al, wh, wl, blin, out, HID, IN_D, SEQ * IN_D);

    copy_tail<<<128, 256>>>(y0, y1, out + (size_t)BATCH * SEQ * IN_D);
}

// round 10
// speedup vs baseline: 2.0849x; 1.0184x over previous
#include <cuda_runtime.h>
#include <cuda_bf16.h>
#include <math.h>
#include <stdint.h>

// Problem constants
#define BATCH 32
#define SEQ   512
#define IN_D  512
#define HID   1024
#define G3    3072   // 3*HID
#define NCTA  128    // persistent scan grid size

typedef unsigned long long ull;

__device__ __forceinline__ uint32_t smem_u32(const void* p) {
    uint32_t a;
    asm("{ .reg .u64 t; cvta.to.shared.u64 t, %1; cvt.u32.u64 %0, t; }" : "=r"(a) : "l"(p));
    return a;
}

// mma.sync / ldmatrix / cp.async (baseline ISA, works on sm_103 target)
#define LDSM_X4(r0, r1, r2, r3, addr) \
    asm volatile("ldmatrix.sync.aligned.m8n8.x4.shared.b16 {%0,%1,%2,%3}, [%4];" \
        : "=r"(r0), "=r"(r1), "=r"(r2), "=r"(r3) : "r"(addr))
#define LDSM_X2(r0, r1, addr) \
    asm volatile("ldmatrix.sync.aligned.m8n8.x2.shared.b16 {%0,%1}, [%2];" \
        : "=r"(r0), "=r"(r1) : "r"(addr))
#define MMA_BF16(d, a, b) \
    asm volatile("mma.sync.aligned.m16n8k16.row.col.f32.bf16.bf16.f32 " \
        "{%0,%1,%2,%3}, {%4,%5,%6,%7}, {%8,%9}, {%0,%1,%2,%3};" \
        : "+f"((d)[0]), "+f"((d)[1]), "+f"((d)[2]), "+f"((d)[3]) \
        : "r"((a)[0]), "r"((a)[1]), "r"((a)[2]), "r"((a)[3]), "r"((b)[0]), "r"((b)[1]))
#define CP16(dst, src) \
    asm volatile("cp.async.cg.shared.global [%0], [%1], 16;" :: "r"(dst), "l"(src))
#define CP_COMMIT() asm volatile("cp.async.commit_group;" ::: "memory")
#define CP_WAIT0()  asm volatile("cp.async.wait_group 0;" ::: "memory")
#define CP_WAIT1()  asm volatile("cp.async.wait_group 1;" ::: "memory")

// ---------------------------------------------------------------------------
// Scratch (device globals)
// ---------------------------------------------------------------------------
__device__ float g_gx[(size_t)SEQ * BATCH * G3];
__device__ float g_y0[(size_t)SEQ * BATCH * HID];
__device__ float g_y1[(size_t)SEQ * BATCH * HID];
__device__ __nv_bfloat16 g_ah[(size_t)SEQ * BATCH * HID];  // A hi [M][K] row-major
__device__ __nv_bfloat16 g_al[(size_t)SEQ * BATCH * HID];  // A lo
__device__ __nv_bfloat16 g_wh[(size_t)G3 * HID];           // W hi [N][K] row-major
__device__ __nv_bfloat16 g_wl[(size_t)G3 * HID];           // W lo
__device__ __align__(16) __nv_bfloat16 g_hb[2][64 * 512];  // h hi, double-buffered, chunked [ch][b][16]
__device__ __align__(16) __nv_bfloat16 g_hl[2][64 * 512];  // h lo

// hierarchical barrier state (zero-init; gens monotonic, counts self-reset)
__device__ unsigned g_gcnt[16 * 64];   // group counters, 256B apart
__device__ unsigned g_ggen[16 * 64];   // group generations, 256B apart
__device__ unsigned g_rcnt;
__device__ unsigned g_rgen;

// ---------------------------------------------------------------------------
// fp32 -> (hi, lo) bf16 split.  Row m of src at (m>>5)*s0 + (m&31)*s1.
// ---------------------------------------------------------------------------
__global__ void conv_split(const float* __restrict__ src, int s0, int s1, int kbits,
                           size_t total, __nv_bfloat16* __restrict__ hi,
                           __nv_bfloat16* __restrict__ lo)
{
    const size_t km = ((size_t)1 << kbits) - 1;
    for (size_t idx = (size_t)blockIdx.x * blockDim.x + threadIdx.x; idx < total;
         idx += (size_t)gridDim.x * blockDim.x) {
        size_t m = idx >> kbits;
        int k = (int)(idx & km);
        float v = src[(m >> 5) * (size_t)s0 + (m & 31) * (size_t)s1 + k];
        __nv_bfloat16 h = __float2bfloat16(v);
        hi[idx] = h;
        lo[idx] = __float2bfloat16(v - __bfloat162float(h));
    }
}

// ---------------------------------------------------------------------------
// mma.sync split-bf16 GEMM (NT) — unchanged from passing rounds 5/7/8/9
// ---------------------------------------------------------------------------
#define TPAD 40
#define TILE_BYTES (128 * TPAD * 2)
#define STAGE_BYTES (4 * TILE_BYTES)

__global__ __launch_bounds__(256)
void gemm_mma(const __nv_bfloat16* __restrict__ Ah, const __nv_bfloat16* __restrict__ Al,
              const __nv_bfloat16* __restrict__ Wh, const __nv_bfloat16* __restrict__ Wl,
              const float* __restrict__ bias, float* __restrict__ C,
              int K, int c_s0, int c_s1)
{
    extern __shared__ char smem[];
    const uint32_t sb = smem_u32(smem);

    const int tid  = threadIdx.x;
    const int wid  = tid >> 5;
    const int lane = tid & 31;
    const int wm   = wid >> 2;
    const int wn   = wid & 3;
    const int bm   = blockIdx.y * 128;
    const int bn   = blockIdx.x * 128;

    const __nv_bfloat16* srcs[4] = { Ah + (size_t)bm * K, Al + (size_t)bm * K,
                                     Wh + (size_t)bn * K, Wl + (size_t)bn * K };

    const int c0 = tid, c1 = tid + 256;
    const int r0 = c0 >> 2, q0 = c0 & 3;
    const int r1 = c1 >> 2, q1 = c1 & 3;

    float acc[4][4][4];
#pragma unroll
    for (int m = 0; m < 4; m++)
#pragma unroll
        for (int n = 0; n < 4; n++)
#pragma unroll
            for (int v = 0; v < 4; v++) acc[m][n][v] = 0.f;

    const int KT = K >> 5;

#pragma unroll
    for (int t = 0; t < 4; t++) {
        const uint32_t db = sb + t * TILE_BYTES;
        CP16(db + r0 * (TPAD * 2) + q0 * 16, srcs[t] + (size_t)r0 * K + q0 * 8);
        CP16(db + r1 * (TPAD * 2) + q1 * 16, srcs[t] + (size_t)r1 * K + q1 * 8);
    }
    CP_COMMIT();

    const int a_row = (lane & 15);
    const int a_colh = (lane >> 4) * 8;
    const int b_row = (lane & 7);
    const int b_colh = ((lane >> 3) & 1) * 8;

    for (int kt = 0; kt < KT; kt++) {
        CP_WAIT0();
        __syncthreads();

        const uint32_t buf = sb + (kt & 1) * STAGE_BYTES;

        if (kt + 1 < KT) {
            const int k0 = (kt + 1) << 5;
            const uint32_t nb = sb + ((kt + 1) & 1) * STAGE_BYTES;
#pragma unroll
            for (int t = 0; t < 4; t++) {
                const uint32_t db = nb + t * TILE_BYTES;
                CP16(db + r0 * (TPAD * 2) + q0 * 16, srcs[t] + (size_t)r0 * K + k0 + q0 * 8);
                CP16(db + r1 * (TPAD * 2) + q1 * 16, srcs[t] + (size_t)r1 * K + k0 + q1 * 8);
            }
            CP_COMMIT();
        }

#pragma unroll
        for (int k16 = 0; k16 < 2; k16++) {
            uint32_t ah4[4][4], al4[4][4], bh2[4][2], bl2[4][2];
#pragma unroll
            for (int m = 0; m < 4; m++) {
                const uint32_t arow = wm * 64 + m * 16 + a_row;
                const uint32_t acol = k16 * 16 + a_colh;
                const uint32_t aoff = arow * (TPAD * 2) + acol * 2;
                LDSM_X4(ah4[m][0], ah4[m][1], ah4[m][2], ah4[m][3], buf + 0 * TILE_BYTES + aoff);
                LDSM_X4(al4[m][0], al4[m][1], al4[m][2], al4[m][3], buf + 1 * TILE_BYTES + aoff);
            }
#pragma unroll
            for (int n = 0; n < 4; n++) {
                const uint32_t brow = wn * 32 + n * 8 + b_row;
                const uint32_t bcol = k16 * 16 + b_colh;
                const uint32_t boff = brow * (TPAD * 2) + bcol * 2;
                LDSM_X2(bh2[n][0], bh2[n][1], buf + 2 * TILE_BYTES + boff);
                LDSM_X2(bl2[n][0], bl2[n][1], buf + 3 * TILE_BYTES + boff);
            }
#pragma unroll
            for (int m = 0; m < 4; m++)
#pragma unroll
                for (int n = 0; n < 4; n++) {
                    MMA_BF16(acc[m][n], ah4[m], bh2[n]);
                    MMA_BF16(acc[m][n], ah4[m], bl2[n]);
                    MMA_BF16(acc[m][n], al4[m], bh2[n]);
                }
        }
        __syncthreads();
    }

    const int qid = lane >> 2;
    const int qtr = lane & 3;
#pragma unroll
    for (int m = 0; m < 4; m++) {
        const int ra = bm + wm * 64 + m * 16 + qid;
        const int rb = ra + 8;
        float* crowa = C + (size_t)(ra >> 5) * c_s0 + (size_t)(ra & 31) * c_s1;
        float* crowb = C + (size_t)(rb >> 5) * c_s0 + (size_t)(rb & 31) * c_s1;
#pragma unroll
        for (int n = 0; n < 4; n++) {
            const int col = bn + wn * 32 + n * 8 + qtr * 2;
            const float bv0 = bias[col], bv1 = bias[col + 1];
            float2 va, vb;
            va.x = acc[m][n][0] + bv0; va.y = acc[m][n][1] + bv1;
            vb.x = acc[m][n][2] + bv0; vb.y = acc[m][n][3] + bv1;
            *(float2*)(crowa + col) = va;
            *(float2*)(crowb + col) = vb;
        }
    }
}

// ---------------------------------------------------------------------------
// grid-wide barrier — two-level tree: 16 groups x 8 CTAs, 16-way root.
// ---------------------------------------------------------------------------
__device__ __forceinline__ void grid_barrier()
{
    __syncthreads();
    if (threadIdx.x == 0) {
        const int g = blockIdx.x >> 3;          // 16 groups of 8
        volatile unsigned* ggen = g_ggen + g * 64;
        unsigned old = *ggen;
        __threadfence();
        if (atomicAdd(&g_gcnt[g * 64], 1u) == 7) {
            unsigned rold = *(volatile unsigned*)&g_rgen;
            if (atomicAdd(&g_rcnt, 1u) == 15) {
                g_rcnt = 0;
                __threadfence();
                atomicAdd(&g_rgen, 1u);
            } else {
                while (*(volatile unsigned*)&g_rgen == rold) { }
            }
            g_gcnt[g * 64] = 0;
            __threadfence();
            atomicAdd(&g_ggen[g * 64], 1u);
        } else {
            while (*ggen == old) { }
        }
        __threadfence();
    }
    __syncthreads();
}

// ---------------------------------------------------------------------------
// Persistent tensor-core GRU scan, v4: one-shot staging split into TWO
// commit groups (64KB each) -> mma on half 0 overlaps the in-flight loads
// of half 1.  Otherwise identical to passing R9 kernel.
// 128 CTAs x 256 thr; CTA owns cols [c*8, c*8+8).
// ---------------------------------------------------------------------------
#define WS_BYTES  98304    // 2 splits * 64 ch * 24 rows * 16 elem * 2B
#define AB_BYTES  131072   // 2 splits * 64 ch * 32 b * 16 elem * 2B (single buf)
#define SCAN_SMEM (WS_BYTES + AB_BYTES)   // 229376

__global__ __launch_bounds__(256, 1)
void gru_scan_mma(const float* __restrict__ gx, const float* __restrict__ Whh,
                  float* __restrict__ y,
                  __nv_bfloat16* __restrict__ yh, __nv_bfloat16* __restrict__ yl,
                  __nv_bfloat16* __restrict__ hbg, __nv_bfloat16* __restrict__ hlg)
{
    extern __shared__ char sm[];
    __nv_bfloat16* ws = (__nv_bfloat16*)sm;
    float* red = (float*)(sm + WS_BYTES);        // aliases A buffer (phase-disjoint)
    const uint32_t sb   = smem_u32(sm);
    const uint32_t WS_B = sb;
    const uint32_t AB_B = sb + WS_BYTES;

    const int tid  = threadIdx.x;
    const int wid  = tid >> 5;
    const int lane = tid & 31;
    const int mi   = wid >> 2;    // m half (batch 0-15 / 16-31)
    const int kq   = wid & 3;     // k quarter
    const int cta  = blockIdx.x;
    const int eb   = tid >> 3;    // epilogue batch
    const int ejj  = tid & 7;     // epilogue col-in-cta
    const int ej   = cta * 8 + ejj;

    // ---- load + split Whh rows into SMEM (once), XOR-swizzled unpadded ----
    for (int i = tid; i < 24 * 1024; i += 256) {
        int r = i >> 10, k = i & 1023;
        int g = r >> 3, jj = r & 7;
        float v = Whh[((size_t)g * HID + cta * 8 + jj) * HID + k];
        __nv_bfloat16 h = __float2bfloat16(v);
        int e = k & 15;
        int off = (k >> 4) * 384 + r * 16 + (((e >> 3) ^ ((r >> 2) & 1)) * 8) + (e & 7);
        ws[off] = h;
        ws[24576 + off] = __float2bfloat16(v - __bfloat162float(h));
    }
    __syncthreads();

    // per-lane constant A offset within a 1KB chunk (row = mi*16 + lane&15)
    const int a_row = mi * 16 + (lane & 15);
    const uint32_t a_off = (uint32_t)a_row * 32 +
                           ((((lane >> 4) ^ ((lane >> 2) & 1)) & 1) << 4);

    float hprev = 0.f;

    for (int s = 0; s < SEQ; s++) {
        // gx prefetch into registers (LDGs overlap the mma phase)
        const float* gp = gx + (size_t)s * (BATCH * G3) + (size_t)eb * G3 + cta * 8 + ejj;
        const float gxr = __ldg(gp);
        const float gxz = __ldg(gp + HID);
        const float gxn = __ldg(gp + 2 * HID);

        float gh0 = 0.f, gh1 = 0.f, gh2 = 0.f;

        if (s > 0) {
            const __nv_bfloat16* hb_rd = hbg + (size_t)((s & 1) ^ 1) * (64 * 512);
            const __nv_bfloat16* hl_rd = hlg + (size_t)((s & 1) ^ 1) * (64 * 512);

            // TWO cp.async commit groups: chunks [0,32) then [32,64), both splits.
            // 16 CP16/thread per group.
#pragma unroll
            for (int grp = 0; grp < 2; grp++) {
#pragma unroll
                for (int it = 0; it < 16; it++) {
                    int i = tid + it * 256;              // 0..4095
                    int split = i >> 11;                 // 2048 per split
                    int rem = i & 2047;
                    int ch = grp * 32 + (rem >> 6);      // 32 chunks per group
                    int b = (rem >> 1) & 31, half = rem & 1;
                    const __nv_bfloat16* src = (split ? hl_rd : hb_rd) +
                                               (size_t)ch * 512 + b * 16 + half * 8;
                    uint32_t dst = AB_B + (uint32_t)split * 65536 + (uint32_t)ch * 1024 +
                                   (uint32_t)b * 32 + (uint32_t)((half ^ ((b >> 2) & 1)) << 4);
                    CP16(dst, src);
                }
                CP_COMMIT();
            }

            float acc[3][4];
#pragma unroll
            for (int t3 = 0; t3 < 3; t3++)
#pragma unroll
                for (int v = 0; v < 4; v++) acc[t3][v] = 0.f;

#pragma unroll
            for (int hf = 0; hf < 2; hf++) {
                if (hf == 0) { CP_WAIT1(); } else { CP_WAIT0(); }
                __syncthreads();

#pragma unroll
                for (int i = 0; i < 8; i++) {
                    const int ch = hf * 32 + kq * 8 + i;
                    const uint32_t ab = AB_B + (uint32_t)ch * 1024 + a_off;
                    uint32_t aH[4], aL[4];
                    LDSM_X4(aH[0], aH[1], aH[2], aH[3], ab);
                    LDSM_X4(aL[0], aL[1], aL[2], aL[3], ab + 65536u);
#pragma unroll
                    for (int t3 = 0; t3 < 3; t3++) {
                        const int brow = t3 * 8 + (lane & 7);
                        const int bh = (lane >> 3) & 1;
                        uint32_t bH[2], bL[2];
                        const uint32_t bbase = WS_B + 2u * (ch * 384 + brow * 16 +
                                             ((bh ^ ((brow >> 2) & 1)) * 8));
                        LDSM_X2(bH[0], bH[1], bbase);
                        LDSM_X2(bL[0], bL[1], bbase + 2u * 24576);
                        MMA_BF16(acc[t3], aH, bH);
                        MMA_BF16(acc[t3], aH, bL);
                        MMA_BF16(acc[t3], aL, bH);
                    }
                }
            }
            __syncthreads();   // mma done -> A buffer free for reduction alias

            // cross-warp k reduction via SMEM (aliases A buffer)
#pragma unroll
            for (int t3 = 0; t3 < 3; t3++) {
                float* rp = red + wid * 384 + (lane >> 2) * 24 + t3 * 8 + (lane & 3) * 2;
                *(float2*)rp = make_float2(acc[t3][0], acc[t3][1]);
                *(float2*)(rp + 8 * 24) = make_float2(acc[t3][2], acc[t3][3]);
            }
            __syncthreads();

            const int mih = eb >> 4, rb = eb & 15;
#pragma unroll
            for (int q = 0; q < 4; q++) {
                const float* rp = red + (mih * 4 + q) * 384 + rb * 24;
                gh0 += rp[ejj];
                gh1 += rp[8 + ejj];
                gh2 += rp[16 + ejj];
            }
        }

        // gate update for (b=eb, j=ej)
        const float r = 1.f / (1.f + __expf(-(gxr + gh0)));
        const float z = 1.f / (1.f + __expf(-(gxz + gh1)));
        const float npre = fmaf(r, gh2, gxn + gh2);
        const float e2 = __expf(2.f * npre);
        const float n = 1.f - 2.f / (e2 + 1.f);
        const float hnew = (1.f - z) * n + z * hprev;
        hprev = hnew;

        // stores: bf16 splits (GEMM A) every step; chunked broadcast; fp32 last step
        if (s == SEQ - 1)
            y[(size_t)eb * HID + ej] = hnew;
        const __nv_bfloat16 hh = __float2bfloat16(hnew);
        const __nv_bfloat16 hl = __float2bfloat16(hnew - __bfloat162float(hh));
        const size_t mrow = ((size_t)s * 32 + eb) * HID + ej;
        yh[mrow] = hh;
        yl[mrow] = hl;
        __nv_bfloat16* hb_wr = hbg + (size_t)(s & 1) * (64 * 512);
        __nv_bfloat16* hl_wr = hlg + (size_t)(s & 1) * (64 * 512);
        const int bidx = (ej >> 4) * 512 + eb * 16 + (ej & 15);
        hb_wr[bidx] = hh;
        hl_wr[bidx] = hl;

        grid_barrier();
    }
}

// ---------------------------------------------------------------------------
// Tail: new_hidden = stack([h_last0, h_last1])
// ---------------------------------------------------------------------------
__global__ void copy_tail(const float* __restrict__ h0,
                          const float* __restrict__ h1,
                          float* __restrict__ dst)
{
    int i = blockIdx.x * blockDim.x + threadIdx.x;
    dst[i]               = h0[i];
    dst[BATCH * HID + i] = h1[i];
}

// ---------------------------------------------------------------------------
// kernel_launch
// ---------------------------------------------------------------------------
extern "C" void kernel_launch(void* const* d_in, const int* in_sizes, int n_in,
                              void* d_out, int out_size)
{
    const float* x    = (const float*)d_in[0];
    const float* Wih0 = (const float*)d_in[1];
    const float* Whh0 = (const float*)d_in[2];
    const float* b0   = (const float*)d_in[3];
    const float* Wih1 = (const float*)d_in[4];
    const float* Whh1 = (const float*)d_in[5];
    const float* b1   = (const float*)d_in[6];
    const float* Wlin = (const float*)d_in[7];
    const float* blin = (const float*)d_in[8];
    float* out = (float*)d_out;

    float *gx, *y0, *y1;
    __nv_bfloat16 *ah, *al, *wh, *wl, *hb, *hl;
    cudaGetSymbolAddress((void**)&gx, g_gx);
    cudaGetSymbolAddress((void**)&y0, g_y0);
    cudaGetSymbolAddress((void**)&y1, g_y1);
    cudaGetSymbolAddress((void**)&ah, g_ah);
    cudaGetSymbolAddress((void**)&al, g_al);
    cudaGetSymbolAddress((void**)&wh, g_wh);
    cudaGetSymbolAddress((void**)&wl, g_wl);
    cudaGetSymbolAddress((void**)&hb, g_hb);
    cudaGetSymbolAddress((void**)&hl, g_hl);

    const int GEMM_SMEM = 2 * STAGE_BYTES;
    cudaFuncSetAttribute(gemm_mma, cudaFuncAttributeMaxDynamicSharedMemorySize, GEMM_SMEM);
    cudaFuncSetAttribute(gru_scan_mma, cudaFuncAttributeMaxDynamicSharedMemorySize, SCAN_SMEM);

    const int M = SEQ * BATCH;   // 16384

    // ---- layer 0 input GEMM: gx = x @ Wih0^T + b0 (time-major rows) ----
    conv_split<<<2048, 256>>>(x, IN_D, SEQ * IN_D, 9, (size_t)M * IN_D, ah, al);
    conv_split<<<2048, 256>>>(Wih0, 32 * IN_D, IN_D, 9, (size_t)G3 * IN_D, wh, wl);
    gemm_mma<<<dim3(G3 / 128, M / 128), 256, GEMM_SMEM>>>(
        ah, al, wh, wl, b0, gx, IN_D, 32 * G3, G3);

    // ---- layer-0 scan (y pointer = last-step slot only) ----
    gru_scan_mma<<<NCTA, 256, SCAN_SMEM>>>(gx, Whh0, y0, ah, al, hb, hl);

    // ---- layer 1 input GEMM: gx = y0 @ Wih1^T + b1 (A splits from scan) ----
    conv_split<<<2048, 256>>>(Wih1, 32 * HID, HID, 10, (size_t)G3 * HID, wh, wl);
    gemm_mma<<<dim3(G3 / 128, M / 128), 256, GEMM_SMEM>>>(
        ah, al, wh, wl, b1, gx, HID, 32 * G3, G3);

    // ---- layer-1 scan ----
    gru_scan_mma<<<NCTA, 256, SCAN_SMEM>>>(gx, Whh1, y1, ah, al, hb, hl);

    // ---- output GEMM: out[b][t][:] = y1 @ Wlin^T + blin ----
    conv_split<<<2048, 256>>>(Wlin, 32 * HID, HID, 10, (size_t)IN_D * HID, wh, wl);
    gemm_mma<<<dim3(IN_D / 128, M / 128), 256, GEMM_SMEM>>>(
        ah, al, wh, wl, blin, out, HID, IN_D, SEQ * IN_D);

    copy_tail<<<128, 256>>>(y0, y1, out + (size_t)BATCH * SEQ * IN_D);
}

// round 11
// speedup vs baseline: 2.8330x; 1.3588x over previous
#include <cuda_runtime.h>
#include <cuda_bf16.h>
#include <math.h>
#include <stdint.h>

// Problem constants
#define BATCH 32
#define SEQ   512
#define IN_D  512
#define HID   1024
#define G3    3072   // 3*HID
#define NCTA  128    // persistent scan grid size

typedef unsigned long long ull;

__device__ __forceinline__ uint32_t smem_u32(const void* p) {
    uint32_t a;
    asm("{ .reg .u64 t; cvta.to.shared.u64 t, %1; cvt.u32.u64 %0, t; }" : "=r"(a) : "l"(p));
    return a;
}

// mma.sync / ldmatrix / cp.async (baseline ISA, works on sm_103 target)
#define LDSM_X4(r0, r1, r2, r3, addr) \
    asm volatile("ldmatrix.sync.aligned.m8n8.x4.shared.b16 {%0,%1,%2,%3}, [%4];" \
        : "=r"(r0), "=r"(r1), "=r"(r2), "=r"(r3) : "r"(addr))
#define LDSM_X2(r0, r1, addr) \
    asm volatile("ldmatrix.sync.aligned.m8n8.x2.shared.b16 {%0,%1}, [%2];" \
        : "=r"(r0), "=r"(r1) : "r"(addr))
#define MMA_BF16(d, a, b) \
    asm volatile("mma.sync.aligned.m16n8k16.row.col.f32.bf16.bf16.f32 " \
        "{%0,%1,%2,%3}, {%4,%5,%6,%7}, {%8,%9}, {%0,%1,%2,%3};" \
        : "+f"((d)[0]), "+f"((d)[1]), "+f"((d)[2]), "+f"((d)[3]) \
        : "r"((a)[0]), "r"((a)[1]), "r"((a)[2]), "r"((a)[3]), "r"((b)[0]), "r"((b)[1]))
#define CP16(dst, src) \
    asm volatile("cp.async.cg.shared.global [%0], [%1], 16;" :: "r"(dst), "l"(src))
#define CP_COMMIT() asm volatile("cp.async.commit_group;" ::: "memory")
#define CP_WAIT0()  asm volatile("cp.async.wait_group 0;" ::: "memory")
#define CP_WAIT1()  asm volatile("cp.async.wait_group 1;" ::: "memory")

// ---------------------------------------------------------------------------
// Scratch (device globals)
// ---------------------------------------------------------------------------
__device__ float g_gx[(size_t)SEQ * BATCH * G3];
__device__ float g_y0[(size_t)SEQ * BATCH * HID];
__device__ float g_y1[(size_t)SEQ * BATCH * HID];
__device__ __nv_bfloat16 g_ah[(size_t)SEQ * BATCH * HID];  // A hi [M][K] row-major
__device__ __nv_bfloat16 g_al[(size_t)SEQ * BATCH * HID];  // A lo
__device__ __nv_bfloat16 g_wh[(size_t)G3 * HID];           // W hi [N][K] row-major
__device__ __nv_bfloat16 g_wl[(size_t)G3 * HID];           // W lo
__device__ __align__(16) __nv_bfloat16 g_hb[2][64 * 512];  // h hi, double-buffered, chunked [ch][b][16]
__device__ __align__(16) __nv_bfloat16 g_hl[2][64 * 512];  // h lo

// per-group producer progress flags (monotonic within a scan launch; reset at end)
__device__ unsigned g_sflag0[8 * 32];   // scan-0 flags, 128B apart
__device__ unsigned g_sflag1[8 * 32];   // scan-1 flags

// final-barrier state (used once per scan; gens monotonic, counts self-reset)
__device__ unsigned g_gcnt[16 * 64];
__device__ unsigned g_ggen[16 * 64];
__device__ unsigned g_rcnt;
__device__ unsigned g_rgen;

// ---------------------------------------------------------------------------
// fp32 -> (hi, lo) bf16 split.  Row m of src at (m>>5)*s0 + (m&31)*s1.
// ---------------------------------------------------------------------------
__global__ void conv_split(const float* __restrict__ src, int s0, int s1, int kbits,
                           size_t total, __nv_bfloat16* __restrict__ hi,
                           __nv_bfloat16* __restrict__ lo)
{
    const size_t km = ((size_t)1 << kbits) - 1;
    for (size_t idx = (size_t)blockIdx.x * blockDim.x + threadIdx.x; idx < total;
         idx += (size_t)gridDim.x * blockDim.x) {
        size_t m = idx >> kbits;
        int k = (int)(idx & km);
        float v = src[(m >> 5) * (size_t)s0 + (m & 31) * (size_t)s1 + k];
        __nv_bfloat16 h = __float2bfloat16(v);
        hi[idx] = h;
        lo[idx] = __float2bfloat16(v - __bfloat162float(h));
    }
}

// ---------------------------------------------------------------------------
// mma.sync split-bf16 GEMM (NT) — unchanged from passing rounds 5/7/8/9/10
// ---------------------------------------------------------------------------
#define TPAD 40
#define TILE_BYTES (128 * TPAD * 2)
#define STAGE_BYTES (4 * TILE_BYTES)

__global__ __launch_bounds__(256)
void gemm_mma(const __nv_bfloat16* __restrict__ Ah, const __nv_bfloat16* __restrict__ Al,
              const __nv_bfloat16* __restrict__ Wh, const __nv_bfloat16* __restrict__ Wl,
              const float* __restrict__ bias, float* __restrict__ C,
              int K, int c_s0, int c_s1)
{
    extern __shared__ char smem[];
    const uint32_t sb = smem_u32(smem);

    const int tid  = threadIdx.x;
    const int wid  = tid >> 5;
    const int lane = tid & 31;
    const int wm   = wid >> 2;
    const int wn   = wid & 3;
    const int bm   = blockIdx.y * 128;
    const int bn   = blockIdx.x * 128;

    const __nv_bfloat16* srcs[4] = { Ah + (size_t)bm * K, Al + (size_t)bm * K,
                                     Wh + (size_t)bn * K, Wl + (size_t)bn * K };

    const int c0 = tid, c1 = tid + 256;
    const int r0 = c0 >> 2, q0 = c0 & 3;
    const int r1 = c1 >> 2, q1 = c1 & 3;

    float acc[4][4][4];
#pragma unroll
    for (int m = 0; m < 4; m++)
#pragma unroll
        for (int n = 0; n < 4; n++)
#pragma unroll
            for (int v = 0; v < 4; v++) acc[m][n][v] = 0.f;

    const int KT = K >> 5;

#pragma unroll
    for (int t = 0; t < 4; t++) {
        const uint32_t db = sb + t * TILE_BYTES;
        CP16(db + r0 * (TPAD * 2) + q0 * 16, srcs[t] + (size_t)r0 * K + q0 * 8);
        CP16(db + r1 * (TPAD * 2) + q1 * 16, srcs[t] + (size_t)r1 * K + q1 * 8);
    }
    CP_COMMIT();

    const int a_row = (lane & 15);
    const int a_colh = (lane >> 4) * 8;
    const int b_row = (lane & 7);
    const int b_colh = ((lane >> 3) & 1) * 8;

    for (int kt = 0; kt < KT; kt++) {
        CP_WAIT0();
        __syncthreads();

        const uint32_t buf = sb + (kt & 1) * STAGE_BYTES;

        if (kt + 1 < KT) {
            const int k0 = (kt + 1) << 5;
            const uint32_t nb = sb + ((kt + 1) & 1) * STAGE_BYTES;
#pragma unroll
            for (int t = 0; t < 4; t++) {
                const uint32_t db = nb + t * TILE_BYTES;
                CP16(db + r0 * (TPAD * 2) + q0 * 16, srcs[t] + (size_t)r0 * K + k0 + q0 * 8);
                CP16(db + r1 * (TPAD * 2) + q1 * 16, srcs[t] + (size_t)r1 * K + k0 + q1 * 8);
            }
            CP_COMMIT();
        }

#pragma unroll
        for (int k16 = 0; k16 < 2; k16++) {
            uint32_t ah4[4][4], al4[4][4], bh2[4][2], bl2[4][2];
#pragma unroll
            for (int m = 0; m < 4; m++) {
                const uint32_t arow = wm * 64 + m * 16 + a_row;
                const uint32_t acol = k16 * 16 + a_colh;
                const uint32_t aoff = arow * (TPAD * 2) + acol * 2;
                LDSM_X4(ah4[m][0], ah4[m][1], ah4[m][2], ah4[m][3], buf + 0 * TILE_BYTES + aoff);
                LDSM_X4(al4[m][0], al4[m][1], al4[m][2], al4[m][3], buf + 1 * TILE_BYTES + aoff);
            }
#pragma unroll
            for (int n = 0; n < 4; n++) {
                const uint32_t brow = wn * 32 + n * 8 + b_row;
                const uint32_t bcol = k16 * 16 + b_colh;
                const uint32_t boff = brow * (TPAD * 2) + bcol * 2;
                LDSM_X2(bh2[n][0], bh2[n][1], buf + 2 * TILE_BYTES + boff);
                LDSM_X2(bl2[n][0], bl2[n][1], buf + 3 * TILE_BYTES + boff);
            }
#pragma unroll
            for (int m = 0; m < 4; m++)
#pragma unroll
                for (int n = 0; n < 4; n++) {
                    MMA_BF16(acc[m][n], ah4[m], bh2[n]);
                    MMA_BF16(acc[m][n], ah4[m], bl2[n]);
                    MMA_BF16(acc[m][n], al4[m], bh2[n]);
                }
        }
        __syncthreads();
    }

    const int qid = lane >> 2;
    const int qtr = lane & 3;
#pragma unroll
    for (int m = 0; m < 4; m++) {
        const int ra = bm + wm * 64 + m * 16 + qid;
        const int rb = ra + 8;
        float* crowa = C + (size_t)(ra >> 5) * c_s0 + (size_t)(ra & 31) * c_s1;
        float* crowb = C + (size_t)(rb >> 5) * c_s0 + (size_t)(rb & 31) * c_s1;
#pragma unroll
        for (int n = 0; n < 4; n++) {
            const int col = bn + wn * 32 + n * 8 + qtr * 2;
            const float bv0 = bias[col], bv1 = bias[col + 1];
            float2 va, vb;
            va.x = acc[m][n][0] + bv0; va.y = acc[m][n][1] + bv1;
            vb.x = acc[m][n][2] + bv0; vb.y = acc[m][n][3] + bv1;
            *(float2*)(crowa + col) = va;
            *(float2*)(crowb + col) = vb;
        }
    }
}

// ---------------------------------------------------------------------------
// grid-wide barrier — two-level tree. Used ONCE per scan (flag reset).
// ---------------------------------------------------------------------------
__device__ __forceinline__ void grid_barrier()
{
    __syncthreads();
    if (threadIdx.x == 0) {
        const int g = blockIdx.x >> 3;
        volatile unsigned* ggen = g_ggen + g * 64;
        unsigned old = *ggen;
        __threadfence();
        if (atomicAdd(&g_gcnt[g * 64], 1u) == 7) {
            unsigned rold = *(volatile unsigned*)&g_rgen;
            if (atomicAdd(&g_rcnt, 1u) == 15) {
                g_rcnt = 0;
                __threadfence();
                atomicAdd(&g_rgen, 1u);
            } else {
                while (*(volatile unsigned*)&g_rgen == rold) { }
            }
            g_gcnt[g * 64] = 0;
            __threadfence();
            atomicAdd(&g_ggen[g * 64], 1u);
        } else {
            while (*ggen == old) { }
        }
        __threadfence();
    }
    __syncthreads();
}

// ---------------------------------------------------------------------------
// Persistent tensor-core GRU scan, v5: per-group producer flags replace the
// per-step global barrier. 128 CTAs x 256 thr; CTA owns cols [c*8, c*8+8).
// 8 column-groups of 16 CTAs; producer CTA flags sflag[c>>4] after storing h.
// Consumer warp w loads AND computes group w (chunks 8w..8w+7): spins on
// sflag[w] >= 16*s, cp.asyncs its own 16KB, mma's its chunks — no syncthreads
// until the cross-warp reduction. Stragglers delay only their group's warp.
// Weights resident in smem (XOR-swizzled, as R8+). Reduction aliases the A
// buffer, protected by the 3 per-step syncs.
// ---------------------------------------------------------------------------
#define WS_BYTES  98304    // 2 splits * 64 ch * 24 rows * 16 elem * 2B
#define AB_BYTES  131072   // 2 splits * 64 ch * 32 b * 16 elem * 2B
#define SCAN_SMEM (WS_BYTES + AB_BYTES)   // 229376

__global__ __launch_bounds__(256, 1)
void gru_scan_mma(const float* __restrict__ gx, const float* __restrict__ Whh,
                  float* __restrict__ y,
                  __nv_bfloat16* __restrict__ yh, __nv_bfloat16* __restrict__ yl,
                  __nv_bfloat16* __restrict__ hbg, __nv_bfloat16* __restrict__ hlg,
                  unsigned* __restrict__ sflag)
{
    extern __shared__ char sm[];
    __nv_bfloat16* ws = (__nv_bfloat16*)sm;
    float* red = (float*)(sm + WS_BYTES);        // aliases A buffer (sync-protected)
    const uint32_t sb   = smem_u32(sm);
    const uint32_t WS_B = sb;
    const uint32_t AB_B = sb + WS_BYTES;

    const int tid  = threadIdx.x;
    const int wid  = tid >> 5;    // warp == group it loads & computes
    const int lane = tid & 31;
    const int cta  = blockIdx.x;
    const int eb   = tid >> 3;    // epilogue batch
    const int ejj  = tid & 7;     // epilogue col-in-cta
    const int ej   = cta * 8 + ejj;
    const int w8   = wid * 8;     // first chunk of this warp's group

    // ---- load + split Whh rows into SMEM (once), XOR-swizzled unpadded ----
    for (int i = tid; i < 24 * 1024; i += 256) {
        int r = i >> 10, k = i & 1023;
        int g = r >> 3, jj = r & 7;
        float v = Whh[((size_t)g * HID + cta * 8 + jj) * HID + k];
        __nv_bfloat16 h = __float2bfloat16(v);
        int e = k & 15;
        int off = (k >> 4) * 384 + r * 16 + (((e >> 3) ^ ((r >> 2) & 1)) * 8) + (e & 7);
        ws[off] = h;
        ws[24576 + off] = __float2bfloat16(v - __bfloat162float(h));
    }
    __syncthreads();

    // per-lane constant A offsets (byte) within a 1KB chunk, per m-half
    const uint32_t a_sw   = ((((lane >> 4) ^ (lane >> 2)) & 1) << 4);
    const uint32_t a_off0 = (uint32_t)(lane & 15) * 32 + a_sw;
    const uint32_t a_off1 = (uint32_t)(16 + (lane & 15)) * 32 + a_sw;

    volatile unsigned* myflag = sflag + wid * 32;

    float hprev = 0.f;

    for (int s = 0; s < SEQ; s++) {
        // gx prefetch into registers (independent of recurrence)
        const float* gp = gx + (size_t)s * (BATCH * G3) + (size_t)eb * G3 + cta * 8 + ejj;
        const float gxr = __ldg(gp);
        const float gxz = __ldg(gp + HID);
        const float gxn = __ldg(gp + 2 * HID);

        float gh0 = 0.f, gh1 = 0.f, gh2 = 0.f;

        if (s > 0) {
            const __nv_bfloat16* hb_rd = hbg + (size_t)((s & 1) ^ 1) * (64 * 512);
            const __nv_bfloat16* hl_rd = hlg + (size_t)((s & 1) ^ 1) * (64 * 512);

            // wait for this warp's group producers (16 CTAs) to finish step s-1
            const unsigned target = 16u * (unsigned)s;
            if (lane == 0) {
                while (*myflag < target) { }
            }
            __syncwarp();

            // this warp loads its own group: 8 chunks x 2 splits = 16KB, 32 CP16/lane
#pragma unroll
            for (int it = 0; it < 32; it++) {
                int i = lane + it * 32;              // 0..1023
                int split = i >> 9;
                int rem = i & 511;
                int chL = rem >> 6;                  // 0..7
                int b = (rem >> 1) & 31, half = rem & 1;
                int ch = w8 + chL;
                const __nv_bfloat16* src = (split ? hl_rd : hb_rd) +
                                           (size_t)ch * 512 + b * 16 + half * 8;
                uint32_t dst = AB_B + (uint32_t)split * 65536 + (uint32_t)ch * 1024 +
                               (uint32_t)b * 32 + (uint32_t)((half ^ ((b >> 2) & 1)) << 4);
                CP16(dst, src);
            }
            CP_COMMIT();
            CP_WAIT0();
            __syncwarp();

            float acc[2][3][4];
#pragma unroll
            for (int mi = 0; mi < 2; mi++)
#pragma unroll
                for (int t3 = 0; t3 < 3; t3++)
#pragma unroll
                    for (int v = 0; v < 4; v++) acc[mi][t3][v] = 0.f;

#pragma unroll
            for (int i = 0; i < 8; i++) {
                const int ch = w8 + i;
                const uint32_t ab = AB_B + (uint32_t)ch * 1024;
                uint32_t aH0[4], aH1[4], aL0[4], aL1[4];
                LDSM_X4(aH0[0], aH0[1], aH0[2], aH0[3], ab + a_off0);
                LDSM_X4(aH1[0], aH1[1], aH1[2], aH1[3], ab + a_off1);
                LDSM_X4(aL0[0], aL0[1], aL0[2], aL0[3], ab + 65536u + a_off0);
                LDSM_X4(aL1[0], aL1[1], aL1[2], aL1[3], ab + 65536u + a_off1);
#pragma unroll
                for (int t3 = 0; t3 < 3; t3++) {
                    const int brow = t3 * 8 + (lane & 7);
                    const int bh = (lane >> 3) & 1;
                    uint32_t bH[2], bL[2];
                    const uint32_t bbase = WS_B + 2u * (ch * 384 + brow * 16 +
                                         ((bh ^ ((brow >> 2) & 1)) * 8));
                    LDSM_X2(bH[0], bH[1], bbase);
                    LDSM_X2(bL[0], bL[1], bbase + 2u * 24576);
                    MMA_BF16(acc[0][t3], aH0, bH);
                    MMA_BF16(acc[0][t3], aH0, bL);
                    MMA_BF16(acc[0][t3], aL0, bH);
                    MMA_BF16(acc[1][t3], aH1, bH);
                    MMA_BF16(acc[1][t3], aH1, bL);
                    MMA_BF16(acc[1][t3], aL1, bH);
                }
            }
            __syncthreads();   // all warps done with A buffer -> red alias safe

            // cross-warp k reduction via SMEM: red[w][32 b][24 jj]
            const int qid = lane >> 2, qtr = lane & 3;
#pragma unroll
            for (int mi = 0; mi < 2; mi++)
#pragma unroll
                for (int t3 = 0; t3 < 3; t3++) {
                    float* rp = red + wid * 768 + (mi * 16 + qid) * 24 + t3 * 8 + qtr * 2;
                    *(float2*)rp = make_float2(acc[mi][t3][0], acc[mi][t3][1]);
                    *(float2*)(rp + 8 * 24) = make_float2(acc[mi][t3][2], acc[mi][t3][3]);
                }
            __syncthreads();

#pragma unroll
            for (int w2 = 0; w2 < 8; w2++) {
                const float* rp = red + w2 * 768 + eb * 24;
                gh0 += rp[ejj];
                gh1 += rp[8 + ejj];
                gh2 += rp[16 + ejj];
            }
        }

        // gate update for (b=eb, j=ej)
        const float r = 1.f / (1.f + __expf(-(gxr + gh0)));
        const float z = 1.f / (1.f + __expf(-(gxz + gh1)));
        const float npre = fmaf(r, gh2, gxn + gh2);
        const float e2 = __expf(2.f * npre);
        const float n = 1.f - 2.f / (e2 + 1.f);
        const float hnew = (1.f - z) * n + z * hprev;
        hprev = hnew;

        // stores: bf16 splits (GEMM A); chunked broadcast; fp32 last step
        if (s == SEQ - 1)
            y[(size_t)eb * HID + ej] = hnew;
        const __nv_bfloat16 hh = __float2bfloat16(hnew);
        const __nv_bfloat16 hl = __float2bfloat16(hnew - __bfloat162float(hh));
        const size_t mrow = ((size_t)s * 32 + eb) * HID + ej;
        yh[mrow] = hh;
        yl[mrow] = hl;
        __nv_bfloat16* hb_wr = hbg + (size_t)(s & 1) * (64 * 512);
        __nv_bfloat16* hl_wr = hlg + (size_t)(s & 1) * (64 * 512);
        const int bidx = (ej >> 4) * 512 + eb * 16 + (ej & 15);
        hb_wr[bidx] = hh;
        hl_wr[bidx] = hl;

        // all threads' stores + red reads done -> flag our group's progress
        __syncthreads();
        if (tid == 0) {
            __threadfence();
            atomicAdd((unsigned*)(sflag + (cta >> 4) * 32), 1u);
        }
    }

    // reset flags for the next launch/replay (after everyone is done)
    grid_barrier();
    if (tid == 0 && cta < 8)
        *(volatile unsigned*)(sflag + cta * 32) = 0u;
}

// ---------------------------------------------------------------------------
// Tail: new_hidden = stack([h_last0, h_last1])
// ---------------------------------------------------------------------------
__global__ void copy_tail(const float* __restrict__ h0,
                          const float* __restrict__ h1,
                          float* __restrict__ dst)
{
    int i = blockIdx.x * blockDim.x + threadIdx.x;
    dst[i]               = h0[i];
    dst[BATCH * HID + i] = h1[i];
}

// ---------------------------------------------------------------------------
// kernel_launch
// ---------------------------------------------------------------------------
extern "C" void kernel_launch(void* const* d_in, const int* in_sizes, int n_in,
                              void* d_out, int out_size)
{
    const float* x    = (const float*)d_in[0];
    const float* Wih0 = (const float*)d_in[1];
    const float* Whh0 = (const float*)d_in[2];
    const float* b0   = (const float*)d_in[3];
    const float* Wih1 = (const float*)d_in[4];
    const float* Whh1 = (const float*)d_in[5];
    const float* b1   = (const float*)d_in[6];
    const float* Wlin = (const float*)d_in[7];
    const float* blin = (const float*)d_in[8];
    float* out = (float*)d_out;

    float *gx, *y0, *y1;
    __nv_bfloat16 *ah, *al, *wh, *wl, *hb, *hl;
    unsigned *sf0, *sf1;
    cudaGetSymbolAddress((void**)&gx, g_gx);
    cudaGetSymbolAddress((void**)&y0, g_y0);
    cudaGetSymbolAddress((void**)&y1, g_y1);
    cudaGetSymbolAddress((void**)&ah, g_ah);
    cudaGetSymbolAddress((void**)&al, g_al);
    cudaGetSymbolAddress((void**)&wh, g_wh);
    cudaGetSymbolAddress((void**)&wl, g_wl);
    cudaGetSymbolAddress((void**)&hb, g_hb);
    cudaGetSymbolAddress((void**)&hl, g_hl);
    cudaGetSymbolAddress((void**)&sf0, g_sflag0);
    cudaGetSymbolAddress((void**)&sf1, g_sflag1);

    const int GEMM_SMEM = 2 * STAGE_BYTES;
    cudaFuncSetAttribute(gemm_mma, cudaFuncAttributeMaxDynamicSharedMemorySize, GEMM_SMEM);
    cudaFuncSetAttribute(gru_scan_mma, cudaFuncAttributeMaxDynamicSharedMemorySize, SCAN_SMEM);

    const int M = SEQ * BATCH;   // 16384

    // ---- layer 0 input GEMM: gx = x @ Wih0^T + b0 (time-major rows) ----
    conv_split<<<2048, 256>>>(x, IN_D, SEQ * IN_D, 9, (size_t)M * IN_D, ah, al);
    conv_split<<<2048, 256>>>(Wih0, 32 * IN_D, IN_D, 9, (size_t)G3 * IN_D, wh, wl);
    gemm_mma<<<dim3(G3 / 128, M / 128), 256, GEMM_SMEM>>>(
        ah, al, wh, wl, b0, gx, IN_D, 32 * G3, G3);

    // ---- layer-0 scan (y pointer = last-step slot only) ----
    gru_scan_mma<<<NCTA, 256, SCAN_SMEM>>>(gx, Whh0, y0, ah, al, hb, hl, sf0);

    // ---- layer 1 input GEMM: gx = y0 @ Wih1^T + b1 (A splits from scan) ----
    conv_split<<<2048, 256>>>(Wih1, 32 * HID, HID, 10, (size_t)G3 * HID, wh, wl);
    gemm_mma<<<dim3(G3 / 128, M / 128), 256, GEMM_SMEM>>>(
        ah, al, wh, wl, b1, gx, HID, 32 * G3, G3);

    // ---- layer-1 scan ----
    gru_scan_mma<<<NCTA, 256, SCAN_SMEM>>>(gx, Whh1, y1, ah, al, hb, hl, sf1);

    // ---- output GEMM: out[b][t][:] = y1 @ Wlin^T + blin ----
    conv_split<<<2048, 256>>>(Wlin, 32 * HID, HID, 10, (size_t)IN_D * HID, wh, wl);
    gemm_mma<<<dim3(IN_D / 128, M / 128), 256, GEMM_SMEM>>>(
        ah, al, wh, wl, blin, out, HID, IN_D, SEQ * IN_D);

    copy_tail<<<128, 256>>>(y0, y1, out + (size_t)BATCH * SEQ * IN_D);
}

// round 12
// speedup vs baseline: 2.8955x; 1.0220x over previous
#include <cuda_runtime.h>
#include <cuda_bf16.h>
#include <math.h>
#include <stdint.h>

// Problem constants
#define BATCH 32
#define SEQ   512
#define IN_D  512
#define HID   1024
#define G3    3072   // 3*HID
#define NCTA  128    // persistent scan grid size

typedef unsigned long long ull;

__device__ __forceinline__ uint32_t smem_u32(const void* p) {
    uint32_t a;
    asm("{ .reg .u64 t; cvta.to.shared.u64 t, %1; cvt.u32.u64 %0, t; }" : "=r"(a) : "l"(p));
    return a;
}

// mma.sync / ldmatrix / cp.async (baseline ISA, works on sm_103 target)
#define LDSM_X4(r0, r1, r2, r3, addr) \
    asm volatile("ldmatrix.sync.aligned.m8n8.x4.shared.b16 {%0,%1,%2,%3}, [%4];" \
        : "=r"(r0), "=r"(r1), "=r"(r2), "=r"(r3) : "r"(addr))
#define LDSM_X2(r0, r1, addr) \
    asm volatile("ldmatrix.sync.aligned.m8n8.x2.shared.b16 {%0,%1}, [%2];" \
        : "=r"(r0), "=r"(r1) : "r"(addr))
#define MMA_BF16(d, a, b) \
    asm volatile("mma.sync.aligned.m16n8k16.row.col.f32.bf16.bf16.f32 " \
        "{%0,%1,%2,%3}, {%4,%5,%6,%7}, {%8,%9}, {%0,%1,%2,%3};" \
        : "+f"((d)[0]), "+f"((d)[1]), "+f"((d)[2]), "+f"((d)[3]) \
        : "r"((a)[0]), "r"((a)[1]), "r"((a)[2]), "r"((a)[3]), "r"((b)[0]), "r"((b)[1]))
#define CP16(dst, src) \
    asm volatile("cp.async.cg.shared.global [%0], [%1], 16;" :: "r"(dst), "l"(src))
#define CP_COMMIT() asm volatile("cp.async.commit_group;" ::: "memory")
#define CP_WAIT0()  asm volatile("cp.async.wait_group 0;" ::: "memory")
#define CP_WAIT1()  asm volatile("cp.async.wait_group 1;" ::: "memory")

// ---------------------------------------------------------------------------
// Scratch (device globals)
// ---------------------------------------------------------------------------
__device__ float g_gx[(size_t)SEQ * BATCH * G3];
__device__ float g_y0[(size_t)SEQ * BATCH * HID];
__device__ float g_y1[(size_t)SEQ * BATCH * HID];
__device__ __nv_bfloat16 g_ah[(size_t)SEQ * BATCH * HID];  // A hi [M][K] row-major
__device__ __nv_bfloat16 g_al[(size_t)SEQ * BATCH * HID];  // A lo
__device__ __nv_bfloat16 g_wh[(size_t)G3 * HID];           // W hi [N][K] row-major
__device__ __nv_bfloat16 g_wl[(size_t)G3 * HID];           // W lo
__device__ __align__(16) __nv_bfloat16 g_hb[2][64 * 512];  // h hi, double-buffered, chunked [ch][b][16]
__device__ __align__(16) __nv_bfloat16 g_hl[2][64 * 512];  // h lo

// per-group producer progress flags (monotonic within a scan launch; reset at end)
__device__ unsigned g_sflag0[8 * 32];   // scan-0 flags, 128B apart
__device__ unsigned g_sflag1[8 * 32];   // scan-1 flags

// final-barrier state (used once per scan; gens monotonic, counts self-reset)
__device__ unsigned g_gcnt[16 * 64];
__device__ unsigned g_ggen[16 * 64];
__device__ unsigned g_rcnt;
__device__ unsigned g_rgen;

// ---------------------------------------------------------------------------
// fp32 -> (hi, lo) bf16 split.  Row m of src at (m>>5)*s0 + (m&31)*s1.
// ---------------------------------------------------------------------------
__global__ void conv_split(const float* __restrict__ src, int s0, int s1, int kbits,
                           size_t total, __nv_bfloat16* __restrict__ hi,
                           __nv_bfloat16* __restrict__ lo)
{
    const size_t km = ((size_t)1 << kbits) - 1;
    for (size_t idx = (size_t)blockIdx.x * blockDim.x + threadIdx.x; idx < total;
         idx += (size_t)gridDim.x * blockDim.x) {
        size_t m = idx >> kbits;
        int k = (int)(idx & km);
        float v = src[(m >> 5) * (size_t)s0 + (m & 31) * (size_t)s1 + k];
        __nv_bfloat16 h = __float2bfloat16(v);
        hi[idx] = h;
        lo[idx] = __float2bfloat16(v - __bfloat162float(h));
    }
}

// ---------------------------------------------------------------------------
// mma.sync split-bf16 GEMM (NT) — unchanged from passing rounds 5/7/8/9/10/11
// ---------------------------------------------------------------------------
#define TPAD 40
#define TILE_BYTES (128 * TPAD * 2)
#define STAGE_BYTES (4 * TILE_BYTES)

__global__ __launch_bounds__(256)
void gemm_mma(const __nv_bfloat16* __restrict__ Ah, const __nv_bfloat16* __restrict__ Al,
              const __nv_bfloat16* __restrict__ Wh, const __nv_bfloat16* __restrict__ Wl,
              const float* __restrict__ bias, float* __restrict__ C,
              int K, int c_s0, int c_s1)
{
    extern __shared__ char smem[];
    const uint32_t sb = smem_u32(smem);

    const int tid  = threadIdx.x;
    const int wid  = tid >> 5;
    const int lane = tid & 31;
    const int wm   = wid >> 2;
    const int wn   = wid & 3;
    const int bm   = blockIdx.y * 128;
    const int bn   = blockIdx.x * 128;

    const __nv_bfloat16* srcs[4] = { Ah + (size_t)bm * K, Al + (size_t)bm * K,
                                     Wh + (size_t)bn * K, Wl + (size_t)bn * K };

    const int c0 = tid, c1 = tid + 256;
    const int r0 = c0 >> 2, q0 = c0 & 3;
    const int r1 = c1 >> 2, q1 = c1 & 3;

    float acc[4][4][4];
#pragma unroll
    for (int m = 0; m < 4; m++)
#pragma unroll
        for (int n = 0; n < 4; n++)
#pragma unroll
            for (int v = 0; v < 4; v++) acc[m][n][v] = 0.f;

    const int KT = K >> 5;

#pragma unroll
    for (int t = 0; t < 4; t++) {
        const uint32_t db = sb + t * TILE_BYTES;
        CP16(db + r0 * (TPAD * 2) + q0 * 16, srcs[t] + (size_t)r0 * K + q0 * 8);
        CP16(db + r1 * (TPAD * 2) + q1 * 16, srcs[t] + (size_t)r1 * K + q1 * 8);
    }
    CP_COMMIT();

    const int a_row = (lane & 15);
    const int a_colh = (lane >> 4) * 8;
    const int b_row = (lane & 7);
    const int b_colh = ((lane >> 3) & 1) * 8;

    for (int kt = 0; kt < KT; kt++) {
        CP_WAIT0();
        __syncthreads();

        const uint32_t buf = sb + (kt & 1) * STAGE_BYTES;

        if (kt + 1 < KT) {
            const int k0 = (kt + 1) << 5;
            const uint32_t nb = sb + ((kt + 1) & 1) * STAGE_BYTES;
#pragma unroll
            for (int t = 0; t < 4; t++) {
                const uint32_t db = nb + t * TILE_BYTES;
                CP16(db + r0 * (TPAD * 2) + q0 * 16, srcs[t] + (size_t)r0 * K + k0 + q0 * 8);
                CP16(db + r1 * (TPAD * 2) + q1 * 16, srcs[t] + (size_t)r1 * K + k0 + q1 * 8);
            }
            CP_COMMIT();
        }

#pragma unroll
        for (int k16 = 0; k16 < 2; k16++) {
            uint32_t ah4[4][4], al4[4][4], bh2[4][2], bl2[4][2];
#pragma unroll
            for (int m = 0; m < 4; m++) {
                const uint32_t arow = wm * 64 + m * 16 + a_row;
                const uint32_t acol = k16 * 16 + a_colh;
                const uint32_t aoff = arow * (TPAD * 2) + acol * 2;
                LDSM_X4(ah4[m][0], ah4[m][1], ah4[m][2], ah4[m][3], buf + 0 * TILE_BYTES + aoff);
                LDSM_X4(al4[m][0], al4[m][1], al4[m][2], al4[m][3], buf + 1 * TILE_BYTES + aoff);
            }
#pragma unroll
            for (int n = 0; n < 4; n++) {
                const uint32_t brow = wn * 32 + n * 8 + b_row;
                const uint32_t bcol = k16 * 16 + b_colh;
                const uint32_t boff = brow * (TPAD * 2) + bcol * 2;
                LDSM_X2(bh2[n][0], bh2[n][1], buf + 2 * TILE_BYTES + boff);
                LDSM_X2(bl2[n][0], bl2[n][1], buf + 3 * TILE_BYTES + boff);
            }
#pragma unroll
            for (int m = 0; m < 4; m++)
#pragma unroll
                for (int n = 0; n < 4; n++) {
                    MMA_BF16(acc[m][n], ah4[m], bh2[n]);
                    MMA_BF16(acc[m][n], ah4[m], bl2[n]);
                    MMA_BF16(acc[m][n], al4[m], bh2[n]);
                }
        }
        __syncthreads();
    }

    const int qid = lane >> 2;
    const int qtr = lane & 3;
#pragma unroll
    for (int m = 0; m < 4; m++) {
        const int ra = bm + wm * 64 + m * 16 + qid;
        const int rb = ra + 8;
        float* crowa = C + (size_t)(ra >> 5) * c_s0 + (size_t)(ra & 31) * c_s1;
        float* crowb = C + (size_t)(rb >> 5) * c_s0 + (size_t)(rb & 31) * c_s1;
#pragma unroll
        for (int n = 0; n < 4; n++) {
            const int col = bn + wn * 32 + n * 8 + qtr * 2;
            const float bv0 = bias[col], bv1 = bias[col + 1];
            float2 va, vb;
            va.x = acc[m][n][0] + bv0; va.y = acc[m][n][1] + bv1;
            vb.x = acc[m][n][2] + bv0; vb.y = acc[m][n][3] + bv1;
            *(float2*)(crowa + col) = va;
            *(float2*)(crowb + col) = vb;
        }
    }
}

// ---------------------------------------------------------------------------
// grid-wide barrier — two-level tree. Used ONCE per scan (flag reset).
// ---------------------------------------------------------------------------
__device__ __forceinline__ void grid_barrier()
{
    __syncthreads();
    if (threadIdx.x == 0) {
        const int g = blockIdx.x >> 3;
        volatile unsigned* ggen = g_ggen + g * 64;
        unsigned old = *ggen;
        __threadfence();
        if (atomicAdd(&g_gcnt[g * 64], 1u) == 7) {
            unsigned rold = *(volatile unsigned*)&g_rgen;
            if (atomicAdd(&g_rcnt, 1u) == 15) {
                g_rcnt = 0;
                __threadfence();
                atomicAdd(&g_rgen, 1u);
            } else {
                while (*(volatile unsigned*)&g_rgen == rold) { }
            }
            g_gcnt[g * 64] = 0;
            __threadfence();
            atomicAdd(&g_ggen[g * 64], 1u);
        } else {
            while (*ggen == old) { }
        }
        __threadfence();
    }
    __syncthreads();
}

// ---------------------------------------------------------------------------
// Persistent tensor-core GRU scan, v6: per-group flags (R11) + two-phase
// hi/lo load-compute pipeline + release/acquire flag synchronization.
// Warp w owns chunk group [8w, 8w+8): loads hi slice (commit grp 1) then lo
// slice (commit grp 2); phase 1 mma (Ah*Wh + Ah*Wl) runs after wait_group 1
// while the lo slice is still in flight; phase 2 (Al*Wh) after wait_group 0.
// ---------------------------------------------------------------------------
#define WS_BYTES  98304    // 2 splits * 64 ch * 24 rows * 16 elem * 2B
#define AB_BYTES  131072   // 2 splits * 64 ch * 32 b * 16 elem * 2B
#define SCAN_SMEM (WS_BYTES + AB_BYTES)   // 229376

__global__ __launch_bounds__(256, 1)
void gru_scan_mma(const float* __restrict__ gx, const float* __restrict__ Whh,
                  float* __restrict__ y,
                  __nv_bfloat16* __restrict__ yh, __nv_bfloat16* __restrict__ yl,
                  __nv_bfloat16* __restrict__ hbg, __nv_bfloat16* __restrict__ hlg,
                  unsigned* __restrict__ sflag)
{
    extern __shared__ char sm[];
    __nv_bfloat16* ws = (__nv_bfloat16*)sm;
    float* red = (float*)(sm + WS_BYTES);        // aliases A buffer (sync-protected)
    const uint32_t sb   = smem_u32(sm);
    const uint32_t WS_B = sb;
    const uint32_t AB_B = sb + WS_BYTES;

    const int tid  = threadIdx.x;
    const int wid  = tid >> 5;    // warp == group it loads & computes
    const int lane = tid & 31;
    const int cta  = blockIdx.x;
    const int eb   = tid >> 3;    // epilogue batch
    const int ejj  = tid & 7;     // epilogue col-in-cta
    const int ej   = cta * 8 + ejj;
    const int w8   = wid * 8;     // first chunk of this warp's group

    // ---- load + split Whh rows into SMEM (once), XOR-swizzled unpadded ----
    for (int i = tid; i < 24 * 1024; i += 256) {
        int r = i >> 10, k = i & 1023;
        int g = r >> 3, jj = r & 7;
        float v = Whh[((size_t)g * HID + cta * 8 + jj) * HID + k];
        __nv_bfloat16 h = __float2bfloat16(v);
        int e = k & 15;
        int off = (k >> 4) * 384 + r * 16 + (((e >> 3) ^ ((r >> 2) & 1)) * 8) + (e & 7);
        ws[off] = h;
        ws[24576 + off] = __float2bfloat16(v - __bfloat162float(h));
    }
    __syncthreads();

    // per-lane constant A offsets (byte) within a 1KB chunk, per m-half
    const uint32_t a_sw   = ((((lane >> 4) ^ (lane >> 2)) & 1) << 4);
    const uint32_t a_off0 = (uint32_t)(lane & 15) * 32 + a_sw;
    const uint32_t a_off1 = (uint32_t)(16 + (lane & 15)) * 32 + a_sw;

    unsigned* myflag = sflag + wid * 32;
    unsigned* grpflag = sflag + (cta >> 4) * 32;

    float hprev = 0.f;

    for (int s = 0; s < SEQ; s++) {
        // gx prefetch into registers (independent of recurrence)
        const float* gp = gx + (size_t)s * (BATCH * G3) + (size_t)eb * G3 + cta * 8 + ejj;
        const float gxr = __ldg(gp);
        const float gxz = __ldg(gp + HID);
        const float gxn = __ldg(gp + 2 * HID);

        float gh0 = 0.f, gh1 = 0.f, gh2 = 0.f;

        if (s > 0) {
            const __nv_bfloat16* hb_rd = hbg + (size_t)((s & 1) ^ 1) * (64 * 512);
            const __nv_bfloat16* hl_rd = hlg + (size_t)((s & 1) ^ 1) * (64 * 512);

            // wait (acquire) for this warp's group producers to finish step s-1
            const unsigned target = 16u * (unsigned)s;
            if (lane == 0) {
                unsigned v;
                do {
                    asm volatile("ld.acquire.gpu.global.u32 %0, [%1];"
                                 : "=r"(v) : "l"(myflag) : "memory");
                } while (v < target);
            }
            __syncwarp();

            // commit group 1: hi slice (8 chunks x 1KB), 16 CP16/lane
#pragma unroll
            for (int it = 0; it < 16; it++) {
                int i = lane + it * 32;              // 0..511
                int chL = i >> 6;                    // 0..7
                int b = (i >> 1) & 31, half = i & 1;
                int ch = w8 + chL;
                const __nv_bfloat16* src = hb_rd + (size_t)ch * 512 + b * 16 + half * 8;
                uint32_t dst = AB_B + (uint32_t)ch * 1024 +
                               (uint32_t)b * 32 + (uint32_t)((half ^ ((b >> 2) & 1)) << 4);
                CP16(dst, src);
            }
            CP_COMMIT();
            // commit group 2: lo slice
#pragma unroll
            for (int it = 0; it < 16; it++) {
                int i = lane + it * 32;
                int chL = i >> 6;
                int b = (i >> 1) & 31, half = i & 1;
                int ch = w8 + chL;
                const __nv_bfloat16* src = hl_rd + (size_t)ch * 512 + b * 16 + half * 8;
                uint32_t dst = AB_B + 65536u + (uint32_t)ch * 1024 +
                               (uint32_t)b * 32 + (uint32_t)((half ^ ((b >> 2) & 1)) << 4);
                CP16(dst, src);
            }
            CP_COMMIT();

            float acc[2][3][4];
#pragma unroll
            for (int mi = 0; mi < 2; mi++)
#pragma unroll
                for (int t3 = 0; t3 < 3; t3++)
#pragma unroll
                    for (int v = 0; v < 4; v++) acc[mi][t3][v] = 0.f;

            // ---- phase 1: hi ready; Ah*Wh + Ah*Wl (lo slice still in flight) ----
            CP_WAIT1();
            __syncwarp();
#pragma unroll
            for (int i = 0; i < 8; i++) {
                const int ch = w8 + i;
                const uint32_t ab = AB_B + (uint32_t)ch * 1024;
                uint32_t aH0[4], aH1[4];
                LDSM_X4(aH0[0], aH0[1], aH0[2], aH0[3], ab + a_off0);
                LDSM_X4(aH1[0], aH1[1], aH1[2], aH1[3], ab + a_off1);
#pragma unroll
                for (int t3 = 0; t3 < 3; t3++) {
                    const int brow = t3 * 8 + (lane & 7);
                    const int bh = (lane >> 3) & 1;
                    uint32_t bH[2], bL[2];
                    const uint32_t bbase = WS_B + 2u * (ch * 384 + brow * 16 +
                                         ((bh ^ ((brow >> 2) & 1)) * 8));
                    LDSM_X2(bH[0], bH[1], bbase);
                    LDSM_X2(bL[0], bL[1], bbase + 2u * 24576);
                    MMA_BF16(acc[0][t3], aH0, bH);
                    MMA_BF16(acc[0][t3], aH0, bL);
                    MMA_BF16(acc[1][t3], aH1, bH);
                    MMA_BF16(acc[1][t3], aH1, bL);
                }
            }

            // ---- phase 2: lo ready; Al*Wh ----
            CP_WAIT0();
            __syncwarp();
#pragma unroll
            for (int i = 0; i < 8; i++) {
                const int ch = w8 + i;
                const uint32_t ab = AB_B + 65536u + (uint32_t)ch * 1024;
                uint32_t aL0[4], aL1[4];
                LDSM_X4(aL0[0], aL0[1], aL0[2], aL0[3], ab + a_off0);
                LDSM_X4(aL1[0], aL1[1], aL1[2], aL1[3], ab + a_off1);
#pragma unroll
                for (int t3 = 0; t3 < 3; t3++) {
                    const int brow = t3 * 8 + (lane & 7);
                    const int bh = (lane >> 3) & 1;
                    uint32_t bH[2];
                    const uint32_t bbase = WS_B + 2u * (ch * 384 + brow * 16 +
                                         ((bh ^ ((brow >> 2) & 1)) * 8));
                    LDSM_X2(bH[0], bH[1], bbase);
                    MMA_BF16(acc[0][t3], aL0, bH);
                    MMA_BF16(acc[1][t3], aL1, bH);
                }
            }
            __syncthreads();   // all warps done with A buffer -> red alias safe

            // cross-warp k reduction via SMEM: red[w][32 b][24 jj]
            const int qid = lane >> 2, qtr = lane & 3;
#pragma unroll
            for (int mi = 0; mi < 2; mi++)
#pragma unroll
                for (int t3 = 0; t3 < 3; t3++) {
                    float* rp = red + wid * 768 + (mi * 16 + qid) * 24 + t3 * 8 + qtr * 2;
                    *(float2*)rp = make_float2(acc[mi][t3][0], acc[mi][t3][1]);
                    *(float2*)(rp + 8 * 24) = make_float2(acc[mi][t3][2], acc[mi][t3][3]);
                }
            __syncthreads();

#pragma unroll
            for (int w2 = 0; w2 < 8; w2++) {
                const float* rp = red + w2 * 768 + eb * 24;
                gh0 += rp[ejj];
                gh1 += rp[8 + ejj];
                gh2 += rp[16 + ejj];
            }
        }

        // gate update for (b=eb, j=ej)
        const float r = 1.f / (1.f + __expf(-(gxr + gh0)));
        const float z = 1.f / (1.f + __expf(-(gxz + gh1)));
        const float npre = fmaf(r, gh2, gxn + gh2);
        const float e2 = __expf(2.f * npre);
        const float n = 1.f - 2.f / (e2 + 1.f);
        const float hnew = (1.f - z) * n + z * hprev;
        hprev = hnew;

        // stores: bf16 splits (GEMM A); chunked broadcast; fp32 last step
        if (s == SEQ - 1)
            y[(size_t)eb * HID + ej] = hnew;
        const __nv_bfloat16 hh = __float2bfloat16(hnew);
        const __nv_bfloat16 hl = __float2bfloat16(hnew - __bfloat162float(hh));
        const size_t mrow = ((size_t)s * 32 + eb) * HID + ej;
        yh[mrow] = hh;
        yl[mrow] = hl;
        __nv_bfloat16* hb_wr = hbg + (size_t)(s & 1) * (64 * 512);
        __nv_bfloat16* hl_wr = hlg + (size_t)(s & 1) * (64 * 512);
        const int bidx = (ej >> 4) * 512 + eb * 16 + (ej & 15);
        hb_wr[bidx] = hh;
        hl_wr[bidx] = hl;

        // all threads' stores + red reads done -> release-flag group progress
        __syncthreads();
        if (tid == 0) {
            asm volatile("red.release.gpu.global.add.u32 [%0], 1;"
                         :: "l"(grpflag) : "memory");
        }
    }

    // reset flags for the next launch/replay (after everyone is done)
    grid_barrier();
    if (tid == 0 && cta < 8)
        *(volatile unsigned*)(sflag + cta * 32) = 0u;
}

// ---------------------------------------------------------------------------
// Tail: new_hidden = stack([h_last0, h_last1])
// ---------------------------------------------------------------------------
__global__ void copy_tail(const float* __restrict__ h0,
                          const float* __restrict__ h1,
                          float* __restrict__ dst)
{
    int i = blockIdx.x * blockDim.x + threadIdx.x;
    dst[i]               = h0[i];
    dst[BATCH * HID + i] = h1[i];
}

// ---------------------------------------------------------------------------
// kernel_launch
// ---------------------------------------------------------------------------
extern "C" void kernel_launch(void* const* d_in, const int* in_sizes, int n_in,
                              void* d_out, int out_size)
{
    const float* x    = (const float*)d_in[0];
    const float* Wih0 = (const float*)d_in[1];
    const float* Whh0 = (const float*)d_in[2];
    const float* b0   = (const float*)d_in[3];
    const float* Wih1 = (const float*)d_in[4];
    const float* Whh1 = (const float*)d_in[5];
    const float* b1   = (const float*)d_in[6];
    const float* Wlin = (const float*)d_in[7];
    const float* blin = (const float*)d_in[8];
    float* out = (float*)d_out;

    float *gx, *y0, *y1;
    __nv_bfloat16 *ah, *al, *wh, *wl, *hb, *hl;
    unsigned *sf0, *sf1;
    cudaGetSymbolAddress((void**)&gx, g_gx);
    cudaGetSymbolAddress((void**)&y0, g_y0);
    cudaGetSymbolAddress((void**)&y1, g_y1);
    cudaGetSymbolAddress((void**)&ah, g_ah);
    cudaGetSymbolAddress((void**)&al, g_al);
    cudaGetSymbolAddress((void**)&wh, g_wh);
    cudaGetSymbolAddress((void**)&wl, g_wl);
    cudaGetSymbolAddress((void**)&hb, g_hb);
    cudaGetSymbolAddress((void**)&hl, g_hl);
    cudaGetSymbolAddress((void**)&sf0, g_sflag0);
    cudaGetSymbolAddress((void**)&sf1, g_sflag1);

    const int GEMM_SMEM = 2 * STAGE_BYTES;
    cudaFuncSetAttribute(gemm_mma, cudaFuncAttributeMaxDynamicSharedMemorySize, GEMM_SMEM);
    cudaFuncSetAttribute(gru_scan_mma, cudaFuncAttributeMaxDynamicSharedMemorySize, SCAN_SMEM);

    const int M = SEQ * BATCH;   // 16384

    // ---- layer 0 input GEMM: gx = x @ Wih0^T + b0 (time-major rows) ----
    conv_split<<<2048, 256>>>(x, IN_D, SEQ * IN_D, 9, (size_t)M * IN_D, ah, al);
    conv_split<<<2048, 256>>>(Wih0, 32 * IN_D, IN_D, 9, (size_t)G3 * IN_D, wh, wl);
    gemm_mma<<<dim3(G3 / 128, M / 128), 256, GEMM_SMEM>>>(
        ah, al, wh, wl, b0, gx, IN_D, 32 * G3, G3);

    // ---- layer-0 scan (y pointer = last-step slot only) ----
    gru_scan_mma<<<NCTA, 256, SCAN_SMEM>>>(gx, Whh0, y0, ah, al, hb, hl, sf0);

    // ---- layer 1 input GEMM: gx = y0 @ Wih1^T + b1 (A splits from scan) ----
    conv_split<<<2048, 256>>>(Wih1, 32 * HID, HID, 10, (size_t)G3 * HID, wh, wl);
    gemm_mma<<<dim3(G3 / 128, M / 128), 256, GEMM_SMEM>>>(
        ah, al, wh, wl, b1, gx, HID, 32 * G3, G3);

    // ---- layer-1 scan ----
    gru_scan_mma<<<NCTA, 256, SCAN_SMEM>>>(gx, Whh1, y1, ah, al, hb, hl, sf1);

    // ---- output GEMM: out[b][t][:] = y1 @ Wlin^T + blin ----
    conv_split<<<2048, 256>>>(Wlin, 32 * HID, HID, 10, (size_t)IN_D * HID, wh, wl);
    gemm_mma<<<dim3(IN_D / 128, M / 128), 256, GEMM_SMEM>>>(
        ah, al, wh, wl, blin, out, HID, IN_D, SEQ * IN_D);

    copy_tail<<<128, 256>>>(y0, y1, out + (size_t)BATCH * SEQ * IN_D);
}